// round 13
// baseline (speedup 1.0000x reference)
#include <cuda_runtime.h>
#include <cuda_bf16.h>
#include <math.h>
#include <stdint.h>

#define FULLMASK 0xffffffffu

// Problem constants
#define B_    8
#define NQ_   900
#define C_    256
#define M_    8
#define D_    32
#define S_    19560
#define FFN_  1024
#define NC_   10
#define R_    (B_*NQ_)            // 7200 rows
#define MT64  ((R_ + 63) / 64)    // 113 M tiles (BM=64)

typedef __nv_bfloat16  bf16;
typedef __nv_bfloat162 bf162;

// ---------------- scratch (static device globals) ----------------
__device__ float g_qout [R_ * 384];        // [off(256) | attn(128)] per row (fp32)
__device__ bf16  g_aggh [R_ * M_ * C_];    // aggregated value rows, bf16
__device__ float g_wsum [R_ * M_];
__device__ bf16  g_featvh[R_ * C_];        // per-head projected features, bf16
__device__ float g_feat [R_ * C_];         // after w_out (fp32, LN input)
__device__ float g_x1   [R_ * C_];         // after LN1 (fp32, residual)
__device__ bf16  g_x1h  [R_ * C_];         // after LN1 (bf16, ffn1 input)
__device__ bf16  g_hh   [R_ * FFN_];       // FFN hidden, bf16
__device__ float g_h2   [R_ * C_];         // after w_ffn2 (fp32)
// bf16 weights [N, K] + bf16 query
__device__ bf16  g_qbf  [R_ * C_];
__device__ bf16  g_wqTh [384 * 256];
__device__ float g_bq   [384];
__device__ bf16  g_woutTh[256 * 256];
__device__ bf16  g_f1Th [1024 * 256];
__device__ bf16  g_f2Th [256 * 1024];
__device__ bf16  g_wvTh [M_ * D_ * 256];   // per-head value-proj slice [8][32][256]

// bf16 m16n8k16 warp MMA
#define MMA_BF16(c, a, b) \
    asm volatile("mma.sync.aligned.m16n8k16.row.col.f32.bf16.bf16.f32 " \
        "{%0,%1,%2,%3}, {%4,%5,%6,%7}, {%8,%9}, {%0,%1,%2,%3};" \
        : "+f"((c)[0]), "+f"((c)[1]), "+f"((c)[2]), "+f"((c)[3]) \
        : "r"((a)[0]), "r"((a)[1]), "r"((a)[2]), "r"((a)[3]), \
          "r"((b)[0]), "r"((b)[1]))

__device__ __forceinline__ void ldsm_x4(uint32_t& r0, uint32_t& r1, uint32_t& r2,
                                        uint32_t& r3, const void* p) {
    uint32_t a = (uint32_t)__cvta_generic_to_shared(p);
    asm volatile("ldmatrix.sync.aligned.m8n8.x4.shared.b16 {%0,%1,%2,%3}, [%4];"
                 : "=r"(r0), "=r"(r1), "=r"(r2), "=r"(r3) : "r"(a));
}
__device__ __forceinline__ void ldsm_x2(uint32_t& r0, uint32_t& r1, const void* p) {
    uint32_t a = (uint32_t)__cvta_generic_to_shared(p);
    asm volatile("ldmatrix.sync.aligned.m8n8.x2.shared.b16 {%0,%1}, [%2];"
                 : "=r"(r0), "=r"(r1) : "r"(a));
}

#define CP_ASYNC16(saddr, gaddr, srcsz) \
    asm volatile("cp.async.cg.shared.global [%0], [%1], 16, %2;" \
        :: "r"(saddr), "l"(gaddr), "r"(srcsz))
#define CP_COMMIT()  asm volatile("cp.async.commit_group;" ::: "memory")
#define CP_WAIT2()   asm volatile("cp.async.wait_group 2;" ::: "memory")

// ---------------- weight / activation prep (all bf16 conversions) ----------------
__global__ __launch_bounds__(256) void prep_weights(
    const float* __restrict__ query,
    const float* __restrict__ w_off, const float* __restrict__ w_attn,
    const float* __restrict__ b_off, const float* __restrict__ b_attn,
    const float* __restrict__ w_out_, const float* __restrict__ w_ffn1,
    const float* __restrict__ w_ffn2, const float* __restrict__ w_value)
{
    int idx = blockIdx.x * 256 + threadIdx.x;
    if (idx < 98304) {                                   // wqTh [384,256]
        int n = idx >> 8, k = idx & 255;
        g_wqTh[idx] = __float2bfloat16_rn((n < 256) ? w_off[k * 256 + n]
                                                    : w_attn[k * 128 + (n - 256)]);
        if (idx < 384) g_bq[idx] = (idx < 256) ? b_off[idx] : b_attn[idx - 256];
        return;
    }
    idx -= 98304;
    if (idx < 65536) {                                   // woutTh [256,256]
        int n = idx >> 8, k = idx & 255;
        g_woutTh[idx] = __float2bfloat16_rn(w_out_[k * 256 + n]);
        return;
    }
    idx -= 65536;
    if (idx < 262144) {                                  // f1Th [1024,256]
        int n = idx >> 8, k = idx & 255;
        g_f1Th[idx] = __float2bfloat16_rn(w_ffn1[k * 1024 + n]);
        return;
    }
    idx -= 262144;
    if (idx < 262144) {                                  // f2Th [256,1024]
        int n = idx >> 10, k = idx & 1023;
        g_f2Th[idx] = __float2bfloat16_rn(w_ffn2[k * 256 + n]);
        return;
    }
    idx -= 262144;
    if (idx < 65536) {                                   // wvTh [8][32][256]
        int m = idx >> 13, n = (idx >> 8) & 31, k = idx & 255;
        g_wvTh[idx] = __float2bfloat16_rn(w_value[k * 256 + m * 32 + n]);
        return;
    }
    idx -= 65536;
    if (idx < R_ * C_ / 4) {                             // qbf (float4 -> 4 bf16)
        float4 v = *(const float4*)&query[idx * 4];
        bf162 p0 = __floats2bfloat162_rn(v.x, v.y);
        bf162 p1 = __floats2bfloat162_rn(v.z, v.w);
        uint2 u;
        u.x = *(uint32_t*)&p0; u.y = *(uint32_t*)&p1;
        *(uint2*)&g_qbf[idx * 4] = u;
        return;
    }
}

// ---------------- bf16 mma GEMM: BM=64, ldmatrix + 4-stage cp.async ----------------
// (unchanged from the 219.2us round)
template<int BN, int EPI, int OBF>
__global__ __launch_bounds__(256) void gemm_bf(
    const bf16* __restrict__ A, int lda, int zA,
    const bf16* __restrict__ WT, int ldb, int zB,
    const float* __restrict__ bias, int zbias,
    const float* __restrict__ wsum,
    void* __restrict__ Cg, int ldc, int zC,
    int Mrows, int Klen)
{
    constexpr int WN = BN / 4;
    constexpr int NJ = WN / 8;
    extern __shared__ float smp[];
    float* As = smp;                    // [4][64][20]
    float* Bs = smp + 4 * 64 * 20;      // [4][BN][20]
#define ASA(s,r,c) As[(((s) << 6) + (r)) * 20 + (c)]
#define BSA(s,r,c) Bs[((s) * BN + (r)) * 20 + (c)]

    const int tid  = threadIdx.x;
    const int wid  = tid >> 5, lane = tid & 31;
    const int g    = lane >> 2, tg = lane & 3;
    const int wm   = (wid & 1) << 5;
    const int wn   = (wid >> 1) * WN;
    const int m0   = blockIdx.x * 64;
    const int n0   = blockIdx.y * BN;
    const int z    = blockIdx.z;

    A    += (size_t)z * zA;
    WT   += (size_t)z * zB;
    bias += z * zbias;

    const int ar  = tid >> 2;
    const int aw  = (tid & 3) << 2;
    const int br  = tid >> 2;
    const int bw  = (tid & 3) << 2;
    const uint32_t aval = ((m0 + ar) < Mrows) ? 16u : 0u;
    const bool bldr = (BN == 64) || (tid < 128);
    const bf16* agp = A  + (size_t)(m0 + ar) * lda + (aw << 1);
    const bf16* bgp = WT + (size_t)(n0 + br) * ldb + (bw << 1);

    const int a_lm_row = wm + (lane & 15);
    const int a_lm_col = (lane >> 4) << 2;
    const int b_lm_row = (BN == 64) ? (wn + ((lane >> 4) << 3) + (lane & 7))
                                    : (wn + (lane & 7));
    const int b_lm_col = ((lane >> 3) & 1) << 2;

    const int niter = Klen >> 5;

    auto issue = [&](int kb, int s) {
        uint32_t sa = (uint32_t)__cvta_generic_to_shared(&ASA(s, ar, aw));
        CP_ASYNC16(sa, agp + (kb << 5), aval);
        if (bldr) {
            uint32_t sb = (uint32_t)__cvta_generic_to_shared(&BSA(s, br, bw));
            CP_ASYNC16(sb, bgp + (kb << 5), 16u);
        }
    };

    float acc[2][NJ][4];
    #pragma unroll
    for (int i = 0; i < 2; i++)
        #pragma unroll
        for (int j = 0; j < NJ; j++)
            #pragma unroll
            for (int v = 0; v < 4; v++) acc[i][j][v] = 0.f;

    issue(0, 0); CP_COMMIT();
    issue(1, 1); CP_COMMIT();
    issue(2, 2); CP_COMMIT();

    for (int it = 0; it < niter; it++) {
        const int s = it & 3;
        CP_WAIT2();
        __syncthreads();
        if (it + 3 < niter) issue(it + 3, (it + 3) & 3);
        CP_COMMIT();

        uint32_t af[2][2][4];
        uint32_t bfr[2][NJ][2];
        #pragma unroll
        for (int kq = 0; kq < 2; kq++) {
            const int ks = kq << 3;
            #pragma unroll
            for (int mi = 0; mi < 2; mi++)
                ldsm_x4(af[kq][mi][0], af[kq][mi][1], af[kq][mi][2], af[kq][mi][3],
                        &ASA(s, a_lm_row + (mi << 4), ks + a_lm_col));
            if (BN == 64) {
                uint32_t r0, r1, r2, r3;
                ldsm_x4(r0, r1, r2, r3, &BSA(s, b_lm_row, ks + b_lm_col));
                bfr[kq][0][0] = r0; bfr[kq][0][1] = r1;
                if (NJ > 1) { bfr[kq][NJ - 1][0] = r2; bfr[kq][NJ - 1][1] = r3; }
            } else {
                ldsm_x2(bfr[kq][0][0], bfr[kq][0][1], &BSA(s, b_lm_row, ks + b_lm_col));
            }
        }
        #pragma unroll
        for (int kq = 0; kq < 2; kq++)
            #pragma unroll
            for (int mi = 0; mi < 2; mi++)
                #pragma unroll
                for (int nj = 0; nj < NJ; nj++)
                    MMA_BF16(acc[mi][nj], af[kq][mi], bfr[kq][nj]);
    }

    #pragma unroll
    for (int nj = 0; nj < NJ; nj++) {
        const int cloc = n0 + wn + (nj << 3) + (tg << 1);
        const int col  = cloc + z * zC;
        const float2 bv = *(const float2*)&bias[cloc];
        #pragma unroll
        for (int mi = 0; mi < 2; mi++) {
            const int row0 = m0 + wm + (mi << 4) + g;
            const int row1 = row0 + 8;
            float2 v0 = make_float2(acc[mi][nj][0], acc[mi][nj][1]);
            float2 v1 = make_float2(acc[mi][nj][2], acc[mi][nj][3]);
            if (EPI == 0) {
                v0.x += bv.x; v0.y += bv.y; v1.x += bv.x; v1.y += bv.y;
            } else if (EPI == 1) {
                v0.x = fmaxf(v0.x + bv.x, 0.f); v0.y = fmaxf(v0.y + bv.y, 0.f);
                v1.x = fmaxf(v1.x + bv.x, 0.f); v1.y = fmaxf(v1.y + bv.y, 0.f);
            }
            if (row0 < Mrows) {
                if (EPI == 2) {
                    const float ws = wsum[(size_t)row0 * 8 + z];
                    v0.x += ws * bv.x; v0.y += ws * bv.y;
                }
                if (OBF) {
                    bf162 p = __floats2bfloat162_rn(v0.x, v0.y);
                    *(bf162*)((bf16*)Cg + (size_t)row0 * ldc + col) = p;
                } else {
                    *(float2*)((float*)Cg + (size_t)row0 * ldc + col) = v0;
                }
            }
            if (row1 < Mrows) {
                if (EPI == 2) {
                    const float ws = wsum[(size_t)row1 * 8 + z];
                    v1.x += ws * bv.x; v1.y += ws * bv.y;
                }
                if (OBF) {
                    bf162 p = __floats2bfloat162_rn(v1.x, v1.y);
                    *(bf162*)((bf16*)Cg + (size_t)row1 * ldc + col) = p;
                } else {
                    *(float2*)((float*)Cg + (size_t)row1 * ldc + col) = v1;
                }
            }
        }
    }
#undef ASA
#undef BSA
}

// ---------------- deformable sampling + aggregation ----------------
// block = one (b,q); warp m = head m. TWO levels per pass: lanes 0-15 own the
// 16 (point,corner) cells of level 2*li, lanes 16-31 those of level 2*li+1.
// Keys are GLOBAL flattened row indices (levels disjoint), so one match_any
// dedups both levels at once; weights of duplicate cells are pre-summed
// (exact linear reassociation) and each distinct row gathered ONCE.
__global__ __launch_bounds__(256) void sample_agg_kernel(
    const float* __restrict__ value, const float* __restrict__ ref_points)
{
    const int r    = blockIdx.x;
    const int b    = r / NQ_;
    const int m    = threadIdx.x >> 5;
    const int lane = threadIdx.x & 31;
    const int half = lane >> 4;

    const float rx = ref_points[r * 2 + 0];
    const float ry = ref_points[r * 2 + 1];

    // softmax over 16 attn logits (lanes 0..15 hold them; lanes 16-31 unused)
    float araw = (lane < 16) ? g_qout[(size_t)r * 384 + 256 + m * 16 + lane] : -1e30f;
    float amax = araw;
    #pragma unroll
    for (int o = 8; o; o >>= 1) amax = fmaxf(amax, __shfl_xor_sync(FULLMASK, amax, o, 16));
    float e = (lane < 16) ? __expf(araw - amax) : 0.f;
    float es = e;
    #pragma unroll
    for (int o = 8; o; o >>= 1) es += __shfl_xor_sync(FULLMASK, es, o, 16);
    const float anorm = e / es;   // valid on lanes 0..15; only those lanes are shfl sources

    const float offv = g_qout[(size_t)r * 384 + m * 32 + lane];

    float a0[4] = {0.f, 0.f, 0.f, 0.f};
    float a1[4] = {0.f, 0.f, 0.f, 0.f};
    float wl_acc = 0.f;

    const int   Hs[4]   = {92, 46, 23, 12};
    const int   Wls[4]  = {160, 80, 40, 20};
    const int   St[4]   = {0, 14720, 18400, 19320};
    const float invWs[4] = {1.f/160.f, 1.f/80.f, 1.f/40.f, 1.f/20.f};
    const float invHs[4] = {1.f/92.f, 1.f/46.f, 1.f/23.f, 1.f/12.f};
    const float* vb = value + (size_t)b * S_ * C_;

#define ACCUM(ptr, wgt) do {                                          \
        const float4* _p4 = (const float4*)(ptr);                     \
        float4 _v0 = _p4[lane];                                       \
        float4 _v1 = _p4[32 + lane];                                  \
        a0[0] = fmaf(wgt, _v0.x, a0[0]);                              \
        a0[1] = fmaf(wgt, _v0.y, a0[1]);                              \
        a0[2] = fmaf(wgt, _v0.z, a0[2]);                              \
        a0[3] = fmaf(wgt, _v0.w, a0[3]);                              \
        a1[0] = fmaf(wgt, _v1.x, a1[0]);                              \
        a1[1] = fmaf(wgt, _v1.y, a1[1]);                              \
        a1[2] = fmaf(wgt, _v1.z, a1[2]);                              \
        a1[3] = fmaf(wgt, _v1.w, a1[3]);                              \
    } while (0)

    #pragma unroll
    for (int li = 0; li < 2; li++) {
        const int l = (li << 1) + half;       // lane-dependent level
        const int Hl = Hs[l], Wl = Wls[l], Stl = St[l];
        const float invW = invWs[l], invH = invHs[l];

        // lane c in 0..15 within this half: point = c>>2, corner = c&3
        const int c   = lane & 15;
        const int ptg = l * 4 + (c >> 2);     // 0..15
        const float a  = __shfl_sync(FULLMASK, anorm, ptg);
        const float ox = __shfl_sync(FULLMASK, offv, 2 * ptg);
        const float oy = __shfl_sync(FULLMASK, offv, 2 * ptg + 1);
        const float x = (rx + ox * invW) * (float)Wl - 0.5f;
        const float y = (ry + oy * invH) * (float)Hl - 0.5f;
        const float xf = floorf(x), yf = floorf(y);
        const float lx = x - xf, ly = y - yf;
        const int xi = (int)xf + (c & 1);
        const int yi = (int)yf + ((c >> 1) & 1);
        const float wx = (c & 1) ? lx : (1.f - lx);
        const float wy = ((c >> 1) & 1) ? ly : (1.f - ly);
        const float w = a * wx * wy;
        const bool valid = ((unsigned)xi < (unsigned)Wl) &&
                           ((unsigned)yi < (unsigned)Hl);
        const int key = valid ? (Stl + yi * Wl + xi) : -1;   // global row index
        const float wl = valid ? w : 0.f;
        wl_acc += wl;

        // one match over the full warp — levels have disjoint key ranges
        const unsigned mm = __match_any_sync(FULLMASK, key);

        // group-summed weight: scan only the lane's own half
        float wtot = 0.f;
        const int jbase = lane & 16;
        #pragma unroll
        for (int j = 0; j < 16; j++) {
            const int jj = jbase + j;
            const float wj = __shfl_sync(FULLMASK, wl, jj);
            if ((mm >> jj) & 1u) wtot += wj;
        }
        const bool leader = valid && ((int)(__ffs(mm) - 1) == lane);

        // gather each distinct row (both levels) once with combined weight
        unsigned bal = __ballot_sync(FULLMASK, leader);
        while (bal) {
            const int src = __ffs(bal) - 1;
            bal &= bal - 1;
            const int   idx = __shfl_sync(FULLMASK, key, src);
            const float wt  = __shfl_sync(FULLMASK, wtot, src);
            ACCUM(vb + (size_t)idx * C_, wt);
        }
    }
#undef ACCUM

    // single wsum reduction at the end (all 32 lanes contribute their levels)
    float wsum = wl_acc;
    #pragma unroll
    for (int o = 16; o; o >>= 1) wsum += __shfl_xor_sync(FULLMASK, wsum, o);

    bf16* ag = g_aggh + ((size_t)r * M_ + m) * C_;
    {
        bf162 p0 = __floats2bfloat162_rn(a0[0], a0[1]);
        bf162 p1 = __floats2bfloat162_rn(a0[2], a0[3]);
        uint2 u; u.x = *(uint32_t*)&p0; u.y = *(uint32_t*)&p1;
        *(uint2*)(ag + lane * 4) = u;
        p0 = __floats2bfloat162_rn(a1[0], a1[1]);
        p1 = __floats2bfloat162_rn(a1[2], a1[3]);
        u.x = *(uint32_t*)&p0; u.y = *(uint32_t*)&p1;
        *(uint2*)(ag + 128 + lane * 4) = u;
    }
    if (lane == 0) g_wsum[(size_t)r * M_ + m] = wsum;
}

// ---------------- LayerNorm helpers ----------------
__global__ __launch_bounds__(256) void ln1_kernel(
    const float* __restrict__ query,
    const float* __restrict__ lw, const float* __restrict__ lb)
{
    const int r = blockIdx.x, t = threadIdx.x;
    const size_t idx = (size_t)r * C_ + t;
    float v = query[idx] + g_feat[idx];

    __shared__ float s1[8], s2[8];
    float sum = v, sq = v * v;
    #pragma unroll
    for (int o = 16; o; o >>= 1) {
        sum += __shfl_xor_sync(FULLMASK, sum, o);
        sq  += __shfl_xor_sync(FULLMASK, sq, o);
    }
    const int lane = t & 31, wp = t >> 5;
    if (lane == 0) { s1[wp] = sum; s2[wp] = sq; }
    __syncthreads();
    float tot = 0.f, totq = 0.f;
    #pragma unroll
    for (int i = 0; i < 8; i++) { tot += s1[i]; totq += s2[i]; }
    const float mu  = tot * (1.f / 256.f);
    const float var = totq * (1.f / 256.f) - mu * mu;
    const float rs  = rsqrtf(var + 1e-6f);
    const float o   = (v - mu) * rs * lw[t] + lb[t];
    g_x1[idx]  = o;
    g_x1h[idx] = __float2bfloat16_rn(o);
}

__global__ __launch_bounds__(256) void ln2_cls_kernel(
    const float* __restrict__ lw, const float* __restrict__ lb,
    const float* __restrict__ wcls, const float* __restrict__ bcls,
    float* __restrict__ out)
{
    const int r = blockIdx.x, t = threadIdx.x;
    const size_t idx = (size_t)r * C_ + t;
    float v = g_x1[idx] + g_h2[idx];

    __shared__ float s1[8], s2[8];
    __shared__ float sred[8][10];
    float sum = v, sq = v * v;
    #pragma unroll
    for (int o = 16; o; o >>= 1) {
        sum += __shfl_xor_sync(FULLMASK, sum, o);
        sq  += __shfl_xor_sync(FULLMASK, sq, o);
    }
    const int lane = t & 31, wp = t >> 5;
    if (lane == 0) { s1[wp] = sum; s2[wp] = sq; }
    __syncthreads();
    float tot = 0.f, totq = 0.f;
    #pragma unroll
    for (int i = 0; i < 8; i++) { tot += s1[i]; totq += s2[i]; }
    const float mu  = tot * (1.f / 256.f);
    const float var = totq * (1.f / 256.f) - mu * mu;
    const float rs  = rsqrtf(var + 1e-6f);
    const float x2  = (v - mu) * rs * lw[t] + lb[t];

    float pr[10];
    #pragma unroll
    for (int j = 0; j < 10; j++) pr[j] = x2 * wcls[t * 10 + j];
    #pragma unroll
    for (int o = 16; o; o >>= 1)
        #pragma unroll
        for (int j = 0; j < 10; j++) pr[j] += __shfl_xor_sync(FULLMASK, pr[j], o);
    if (lane == 0)
        #pragma unroll
        for (int j = 0; j < 10; j++) sred[wp][j] = pr[j];
    __syncthreads();
    if (t < 10) {
        float s = bcls[t];
        #pragma unroll
        for (int i = 0; i < 8; i++) s += sred[i][t];
        out[(size_t)r * NC_ + t] = s;
    }
}

// ---------------- launch ----------------
#define SMEM64 ((4*64*20 + 4*64*20) * 4)   // 40960
#define SMEM32 ((4*64*20 + 4*32*20) * 4)   // 30720

extern "C" void kernel_launch(void* const* d_in, const int* in_sizes, int n_in,
                              void* d_out, int out_size)
{
    const float* query  = (const float*)d_in[0];
    const float* value  = (const float*)d_in[1];
    const float* refp   = (const float*)d_in[2];
    const float* w_value= (const float*)d_in[3];
    const float* b_value= (const float*)d_in[4];
    const float* w_off  = (const float*)d_in[5];
    const float* b_off  = (const float*)d_in[6];
    const float* w_attn = (const float*)d_in[7];
    const float* b_attn = (const float*)d_in[8];
    const float* w_out  = (const float*)d_in[9];
    const float* b_out  = (const float*)d_in[10];
    const float* ln1w   = (const float*)d_in[11];
    const float* ln1b   = (const float*)d_in[12];
    const float* w_ffn1 = (const float*)d_in[13];
    const float* b_ffn1 = (const float*)d_in[14];
    const float* w_ffn2 = (const float*)d_in[15];
    const float* b_ffn2 = (const float*)d_in[16];
    const float* ln2w   = (const float*)d_in[17];
    const float* ln2b   = (const float*)d_in[18];
    const float* w_cls  = (const float*)d_in[19];
    const float* b_cls  = (const float*)d_in[20];
    float* out = (float*)d_out;

    float *p_qout, *p_wsum, *p_feat, *p_x1, *p_h2, *p_bq;
    bf16  *p_aggh, *p_featvh, *p_x1h, *p_hh, *p_qbf;
    bf16  *p_wqTh, *p_woutTh, *p_f1Th, *p_f2Th, *p_wvTh;
    cudaGetSymbolAddress((void**)&p_qout,   g_qout);
    cudaGetSymbolAddress((void**)&p_aggh,   g_aggh);
    cudaGetSymbolAddress((void**)&p_wsum,   g_wsum);
    cudaGetSymbolAddress((void**)&p_featvh, g_featvh);
    cudaGetSymbolAddress((void**)&p_feat,   g_feat);
    cudaGetSymbolAddress((void**)&p_x1,     g_x1);
    cudaGetSymbolAddress((void**)&p_x1h,    g_x1h);
    cudaGetSymbolAddress((void**)&p_hh,     g_hh);
    cudaGetSymbolAddress((void**)&p_h2,     g_h2);
    cudaGetSymbolAddress((void**)&p_qbf,    g_qbf);
    cudaGetSymbolAddress((void**)&p_wqTh,   g_wqTh);
    cudaGetSymbolAddress((void**)&p_bq,     g_bq);
    cudaGetSymbolAddress((void**)&p_woutTh, g_woutTh);
    cudaGetSymbolAddress((void**)&p_f1Th,   g_f1Th);
    cudaGetSymbolAddress((void**)&p_f2Th,   g_f2Th);
    cudaGetSymbolAddress((void**)&p_wvTh,   g_wvTh);

    cudaFuncSetAttribute(gemm_bf<64,0,0>, cudaFuncAttributeMaxDynamicSharedMemorySize, SMEM64);
    cudaFuncSetAttribute(gemm_bf<64,1,1>, cudaFuncAttributeMaxDynamicSharedMemorySize, SMEM64);
    cudaFuncSetAttribute(gemm_bf<32,2,1>, cudaFuncAttributeMaxDynamicSharedMemorySize, SMEM32);

    // 0. weight + query bf16 prep
    prep_weights<<<9990, 256>>>(query, w_off, w_attn, b_off, b_attn,
                                w_out, w_ffn1, w_ffn2, w_value);
    // 1. fused query projection: [off | attn] = q @ [w_off | w_attn]   grid 678
    gemm_bf<64,0,0><<<dim3(MT64, 6), 256, SMEM64>>>(p_qbf, C_, 0, p_wqTh, 256, 0, p_bq, 0,
                                                    nullptr, p_qout, 384, 0, R_, 256);
    // 2. deformable sampling + weighted aggregation (2-level vectorized dedup)
    sample_agg_kernel<<<R_, 256>>>(value, refp);
    // 3. per-head value projection (thin GEMM N=32 per head)   grid 904
    gemm_bf<32,2,1><<<dim3(MT64, 1, M_), 256, SMEM32>>>(p_aggh, 2048, 256, p_wvTh, 256, 8192,
                                                        b_value, 32, p_wsum,
                                                        p_featvh, C_, 32, R_, 256);
    // 4. output projection (fp32 out for LN)   grid 452
    gemm_bf<64,0,0><<<dim3(MT64, 4), 256, SMEM64>>>(p_featvh, C_, 0, p_woutTh, 256, 0, b_out, 0,
                                                    nullptr, p_feat, C_, 0, R_, 256);
    // 5. residual + LN1 (fp32 + bf16 mirror)
    ln1_kernel<<<R_, 256>>>(query, ln1w, ln1b);
    // 6. FFN   grids 1808 / 452
    gemm_bf<64,1,1><<<dim3(MT64, 16), 256, SMEM64>>>(p_x1h, C_, 0, p_f1Th, 256, 0, b_ffn1, 0,
                                                     nullptr, p_hh, FFN_, 0, R_, 256);
    gemm_bf<64,0,0><<<dim3(MT64, 4), 256, SMEM64>>>(p_hh, FFN_, 0, p_f2Th, 1024, 0, b_ffn2, 0,
                                                    nullptr, p_h2, C_, 0, R_, 1024);
    // 7. residual + LN2 + classifier
    ln2_cls_kernel<<<R_, 256>>>(ln2w, ln2b, w_cls, b_cls, out);
}

// round 14
// speedup vs baseline: 1.0388x; 1.0388x over previous
#include <cuda_runtime.h>
#include <cuda_bf16.h>
#include <math.h>
#include <stdint.h>

#define FULLMASK 0xffffffffu

// Problem constants
#define B_    8
#define NQ_   900
#define C_    256
#define M_    8
#define D_    32
#define S_    19560
#define FFN_  1024
#define NC_   10
#define R_    (B_*NQ_)            // 7200 rows
#define MT64  ((R_ + 63) / 64)    // 113 M tiles (BM=64)

typedef __nv_bfloat16  bf16;
typedef __nv_bfloat162 bf162;

// ---------------- scratch (static device globals) ----------------
__device__ float g_qout [R_ * 384];        // [off(256) | attn(128)] per row (fp32)
__device__ bf16  g_aggh [R_ * M_ * C_];    // aggregated value rows, bf16
__device__ float g_wsum [R_ * M_];
__device__ bf16  g_featvh[R_ * C_];        // per-head projected features, bf16
__device__ float g_feat [R_ * C_];         // after w_out (fp32, LN input)
__device__ float g_x1   [R_ * C_];         // after LN1 (fp32, residual)
__device__ bf16  g_x1h  [R_ * C_];         // after LN1 (bf16, ffn1 input)
__device__ bf16  g_hh   [R_ * FFN_];       // FFN hidden, bf16
__device__ float g_h2   [R_ * C_];         // after w_ffn2 (fp32)
// bf16 weights [N, K] + bf16 query
__device__ bf16  g_qbf  [R_ * C_];
__device__ bf16  g_wqTh [384 * 256];
__device__ float g_bq   [384];
__device__ bf16  g_woutTh[256 * 256];
__device__ bf16  g_f1Th [1024 * 256];
__device__ bf16  g_f2Th [256 * 1024];
__device__ bf16  g_wvTh [M_ * D_ * 256];   // per-head value-proj slice [8][32][256]

// bf16 m16n8k16 warp MMA
#define MMA_BF16(c, a, b) \
    asm volatile("mma.sync.aligned.m16n8k16.row.col.f32.bf16.bf16.f32 " \
        "{%0,%1,%2,%3}, {%4,%5,%6,%7}, {%8,%9}, {%0,%1,%2,%3};" \
        : "+f"((c)[0]), "+f"((c)[1]), "+f"((c)[2]), "+f"((c)[3]) \
        : "r"((a)[0]), "r"((a)[1]), "r"((a)[2]), "r"((a)[3]), \
          "r"((b)[0]), "r"((b)[1]))

__device__ __forceinline__ void ldsm_x4(uint32_t& r0, uint32_t& r1, uint32_t& r2,
                                        uint32_t& r3, const void* p) {
    uint32_t a = (uint32_t)__cvta_generic_to_shared(p);
    asm volatile("ldmatrix.sync.aligned.m8n8.x4.shared.b16 {%0,%1,%2,%3}, [%4];"
                 : "=r"(r0), "=r"(r1), "=r"(r2), "=r"(r3) : "r"(a));
}
__device__ __forceinline__ void ldsm_x2(uint32_t& r0, uint32_t& r1, const void* p) {
    uint32_t a = (uint32_t)__cvta_generic_to_shared(p);
    asm volatile("ldmatrix.sync.aligned.m8n8.x2.shared.b16 {%0,%1}, [%2];"
                 : "=r"(r0), "=r"(r1) : "r"(a));
}

#define CP_ASYNC16(saddr, gaddr, srcsz) \
    asm volatile("cp.async.cg.shared.global [%0], [%1], 16, %2;" \
        :: "r"(saddr), "l"(gaddr), "r"(srcsz))
#define CP_COMMIT()  asm volatile("cp.async.commit_group;" ::: "memory")
#define CP_WAIT2()   asm volatile("cp.async.wait_group 2;" ::: "memory")

// ---------------- weight / activation prep (all bf16 conversions) ----------------
__global__ __launch_bounds__(256) void prep_weights(
    const float* __restrict__ query,
    const float* __restrict__ w_off, const float* __restrict__ w_attn,
    const float* __restrict__ b_off, const float* __restrict__ b_attn,
    const float* __restrict__ w_out_, const float* __restrict__ w_ffn1,
    const float* __restrict__ w_ffn2, const float* __restrict__ w_value)
{
    int idx = blockIdx.x * 256 + threadIdx.x;
    if (idx < 98304) {                                   // wqTh [384,256]
        int n = idx >> 8, k = idx & 255;
        g_wqTh[idx] = __float2bfloat16_rn((n < 256) ? w_off[k * 256 + n]
                                                    : w_attn[k * 128 + (n - 256)]);
        if (idx < 384) g_bq[idx] = (idx < 256) ? b_off[idx] : b_attn[idx - 256];
        return;
    }
    idx -= 98304;
    if (idx < 65536) {                                   // woutTh [256,256]
        int n = idx >> 8, k = idx & 255;
        g_woutTh[idx] = __float2bfloat16_rn(w_out_[k * 256 + n]);
        return;
    }
    idx -= 65536;
    if (idx < 262144) {                                  // f1Th [1024,256]
        int n = idx >> 8, k = idx & 255;
        g_f1Th[idx] = __float2bfloat16_rn(w_ffn1[k * 1024 + n]);
        return;
    }
    idx -= 262144;
    if (idx < 262144) {                                  // f2Th [256,1024]
        int n = idx >> 10, k = idx & 1023;
        g_f2Th[idx] = __float2bfloat16_rn(w_ffn2[k * 256 + n]);
        return;
    }
    idx -= 262144;
    if (idx < 65536) {                                   // wvTh [8][32][256]
        int m = idx >> 13, n = (idx >> 8) & 31, k = idx & 255;
        g_wvTh[idx] = __float2bfloat16_rn(w_value[k * 256 + m * 32 + n]);
        return;
    }
    idx -= 65536;
    if (idx < R_ * C_ / 4) {                             // qbf (float4 -> 4 bf16)
        float4 v = *(const float4*)&query[idx * 4];
        bf162 p0 = __floats2bfloat162_rn(v.x, v.y);
        bf162 p1 = __floats2bfloat162_rn(v.z, v.w);
        uint2 u;
        u.x = *(uint32_t*)&p0; u.y = *(uint32_t*)&p1;
        *(uint2*)&g_qbf[idx * 4] = u;
        return;
    }
}

// ---------------- bf16 mma GEMM: BM=64, ldmatrix + 4-stage cp.async ----------------
// (identical to the 219.2us round-12 kernel)
template<int BN, int EPI, int OBF>
__global__ __launch_bounds__(256) void gemm_bf(
    const bf16* __restrict__ A, int lda, int zA,
    const bf16* __restrict__ WT, int ldb, int zB,
    const float* __restrict__ bias, int zbias,
    const float* __restrict__ wsum,
    void* __restrict__ Cg, int ldc, int zC,
    int Mrows, int Klen)
{
    constexpr int WN = BN / 4;
    constexpr int NJ = WN / 8;
    extern __shared__ float smp[];
    float* As = smp;                    // [4][64][20]
    float* Bs = smp + 4 * 64 * 20;      // [4][BN][20]
#define ASA(s,r,c) As[(((s) << 6) + (r)) * 20 + (c)]
#define BSA(s,r,c) Bs[((s) * BN + (r)) * 20 + (c)]

    const int tid  = threadIdx.x;
    const int wid  = tid >> 5, lane = tid & 31;
    const int g    = lane >> 2, tg = lane & 3;
    const int wm   = (wid & 1) << 5;
    const int wn   = (wid >> 1) * WN;
    const int m0   = blockIdx.x * 64;
    const int n0   = blockIdx.y * BN;
    const int z    = blockIdx.z;

    A    += (size_t)z * zA;
    WT   += (size_t)z * zB;
    bias += z * zbias;

    const int ar  = tid >> 2;
    const int aw  = (tid & 3) << 2;
    const int br  = tid >> 2;
    const int bw  = (tid & 3) << 2;
    const uint32_t aval = ((m0 + ar) < Mrows) ? 16u : 0u;
    const bool bldr = (BN == 64) || (tid < 128);
    const bf16* agp = A  + (size_t)(m0 + ar) * lda + (aw << 1);
    const bf16* bgp = WT + (size_t)(n0 + br) * ldb + (bw << 1);

    const int a_lm_row = wm + (lane & 15);
    const int a_lm_col = (lane >> 4) << 2;
    const int b_lm_row = (BN == 64) ? (wn + ((lane >> 4) << 3) + (lane & 7))
                                    : (wn + (lane & 7));
    const int b_lm_col = ((lane >> 3) & 1) << 2;

    const int niter = Klen >> 5;

    auto issue = [&](int kb, int s) {
        uint32_t sa = (uint32_t)__cvta_generic_to_shared(&ASA(s, ar, aw));
        CP_ASYNC16(sa, agp + (kb << 5), aval);
        if (bldr) {
            uint32_t sb = (uint32_t)__cvta_generic_to_shared(&BSA(s, br, bw));
            CP_ASYNC16(sb, bgp + (kb << 5), 16u);
        }
    };

    float acc[2][NJ][4];
    #pragma unroll
    for (int i = 0; i < 2; i++)
        #pragma unroll
        for (int j = 0; j < NJ; j++)
            #pragma unroll
            for (int v = 0; v < 4; v++) acc[i][j][v] = 0.f;

    issue(0, 0); CP_COMMIT();
    issue(1, 1); CP_COMMIT();
    issue(2, 2); CP_COMMIT();

    for (int it = 0; it < niter; it++) {
        const int s = it & 3;
        CP_WAIT2();
        __syncthreads();
        if (it + 3 < niter) issue(it + 3, (it + 3) & 3);
        CP_COMMIT();

        uint32_t af[2][2][4];
        uint32_t bfr[2][NJ][2];
        #pragma unroll
        for (int kq = 0; kq < 2; kq++) {
            const int ks = kq << 3;
            #pragma unroll
            for (int mi = 0; mi < 2; mi++)
                ldsm_x4(af[kq][mi][0], af[kq][mi][1], af[kq][mi][2], af[kq][mi][3],
                        &ASA(s, a_lm_row + (mi << 4), ks + a_lm_col));
            if (BN == 64) {
                uint32_t r0, r1, r2, r3;
                ldsm_x4(r0, r1, r2, r3, &BSA(s, b_lm_row, ks + b_lm_col));
                bfr[kq][0][0] = r0; bfr[kq][0][1] = r1;
                if (NJ > 1) { bfr[kq][NJ - 1][0] = r2; bfr[kq][NJ - 1][1] = r3; }
            } else {
                ldsm_x2(bfr[kq][0][0], bfr[kq][0][1], &BSA(s, b_lm_row, ks + b_lm_col));
            }
        }
        #pragma unroll
        for (int kq = 0; kq < 2; kq++)
            #pragma unroll
            for (int mi = 0; mi < 2; mi++)
                #pragma unroll
                for (int nj = 0; nj < NJ; nj++)
                    MMA_BF16(acc[mi][nj], af[kq][mi], bfr[kq][nj]);
    }

    #pragma unroll
    for (int nj = 0; nj < NJ; nj++) {
        const int cloc = n0 + wn + (nj << 3) + (tg << 1);
        const int col  = cloc + z * zC;
        const float2 bv = *(const float2*)&bias[cloc];
        #pragma unroll
        for (int mi = 0; mi < 2; mi++) {
            const int row0 = m0 + wm + (mi << 4) + g;
            const int row1 = row0 + 8;
            float2 v0 = make_float2(acc[mi][nj][0], acc[mi][nj][1]);
            float2 v1 = make_float2(acc[mi][nj][2], acc[mi][nj][3]);
            if (EPI == 0) {
                v0.x += bv.x; v0.y += bv.y; v1.x += bv.x; v1.y += bv.y;
            } else if (EPI == 1) {
                v0.x = fmaxf(v0.x + bv.x, 0.f); v0.y = fmaxf(v0.y + bv.y, 0.f);
                v1.x = fmaxf(v1.x + bv.x, 0.f); v1.y = fmaxf(v1.y + bv.y, 0.f);
            }
            if (row0 < Mrows) {
                if (EPI == 2) {
                    const float ws = wsum[(size_t)row0 * 8 + z];
                    v0.x += ws * bv.x; v0.y += ws * bv.y;
                }
                if (OBF) {
                    bf162 p = __floats2bfloat162_rn(v0.x, v0.y);
                    *(bf162*)((bf16*)Cg + (size_t)row0 * ldc + col) = p;
                } else {
                    *(float2*)((float*)Cg + (size_t)row0 * ldc + col) = v0;
                }
            }
            if (row1 < Mrows) {
                if (EPI == 2) {
                    const float ws = wsum[(size_t)row1 * 8 + z];
                    v1.x += ws * bv.x; v1.y += ws * bv.y;
                }
                if (OBF) {
                    bf162 p = __floats2bfloat162_rn(v1.x, v1.y);
                    *(bf162*)((bf16*)Cg + (size_t)row1 * ldc + col) = p;
                } else {
                    *(float2*)((float*)Cg + (size_t)row1 * ldc + col) = v1;
                }
            }
        }
    }
#undef ASA
#undef BSA
}

// ---------------- deformable sampling + aggregation (R12 form + ILP-2 gather) --------
__global__ __launch_bounds__(256) void sample_agg_kernel(
    const float* __restrict__ value, const float* __restrict__ ref_points)
{
    const int r    = blockIdx.x;
    const int b    = r / NQ_;
    const int m    = threadIdx.x >> 5;
    const int lane = threadIdx.x & 31;

    const float rx = ref_points[r * 2 + 0];
    const float ry = ref_points[r * 2 + 1];

    float araw = (lane < 16) ? g_qout[(size_t)r * 384 + 256 + m * 16 + lane] : -1e30f;
    float amax = araw;
    #pragma unroll
    for (int o = 8; o; o >>= 1) amax = fmaxf(amax, __shfl_xor_sync(FULLMASK, amax, o, 16));
    float e = (lane < 16) ? __expf(araw - amax) : 0.f;
    float es = e;
    #pragma unroll
    for (int o = 8; o; o >>= 1) es += __shfl_xor_sync(FULLMASK, es, o, 16);
    const float anorm = e / es;

    const float offv = g_qout[(size_t)r * 384 + m * 32 + lane];

    float a0[4] = {0.f, 0.f, 0.f, 0.f};
    float a1[4] = {0.f, 0.f, 0.f, 0.f};
    float wl_acc = 0.f;

    const int Hs[4]  = {92, 46, 23, 12};
    const int Wls[4] = {160, 80, 40, 20};
    const int St[4]  = {0, 14720, 18400, 19320};
    const float* vb = value + (size_t)b * S_ * C_;

#define ACCUM1(ptr, wgt) do {                                         \
        const float4* _p4 = (const float4*)(ptr);                     \
        float4 _v0 = _p4[lane];                                       \
        float4 _v1 = _p4[32 + lane];                                  \
        a0[0] = fmaf(wgt, _v0.x, a0[0]);                              \
        a0[1] = fmaf(wgt, _v0.y, a0[1]);                              \
        a0[2] = fmaf(wgt, _v0.z, a0[2]);                              \
        a0[3] = fmaf(wgt, _v0.w, a0[3]);                              \
        a1[0] = fmaf(wgt, _v1.x, a1[0]);                              \
        a1[1] = fmaf(wgt, _v1.y, a1[1]);                              \
        a1[2] = fmaf(wgt, _v1.z, a1[2]);                              \
        a1[3] = fmaf(wgt, _v1.w, a1[3]);                              \
    } while (0)

#define ACCUM2(p0, w0, p1, w1) do {                                   \
        const float4* _q0 = (const float4*)(p0);                      \
        const float4* _q1 = (const float4*)(p1);                      \
        float4 _x0 = _q0[lane];                                       \
        float4 _x1 = _q0[32 + lane];                                  \
        float4 _y0 = _q1[lane];                                       \
        float4 _y1 = _q1[32 + lane];                                  \
        a0[0] = fmaf(w0, _x0.x, a0[0]);                               \
        a0[1] = fmaf(w0, _x0.y, a0[1]);                               \
        a0[2] = fmaf(w0, _x0.z, a0[2]);                               \
        a0[3] = fmaf(w0, _x0.w, a0[3]);                               \
        a1[0] = fmaf(w0, _x1.x, a1[0]);                               \
        a1[1] = fmaf(w0, _x1.y, a1[1]);                               \
        a1[2] = fmaf(w0, _x1.z, a1[2]);                               \
        a1[3] = fmaf(w0, _x1.w, a1[3]);                               \
        a0[0] = fmaf(w1, _y0.x, a0[0]);                               \
        a0[1] = fmaf(w1, _y0.y, a0[1]);                               \
        a0[2] = fmaf(w1, _y0.z, a0[2]);                               \
        a0[3] = fmaf(w1, _y0.w, a0[3]);                               \
        a1[0] = fmaf(w1, _y1.x, a1[0]);                               \
        a1[1] = fmaf(w1, _y1.y, a1[1]);                               \
        a1[2] = fmaf(w1, _y1.z, a1[2]);                               \
        a1[3] = fmaf(w1, _y1.w, a1[3]);                               \
    } while (0)

    #pragma unroll
    for (int l = 0; l < 4; l++) {
        const int Hl = Hs[l], Wl = Wls[l];
        const float invW = 1.f / (float)Wl, invH = 1.f / (float)Hl;
        const float* lb = vb + (size_t)St[l] * C_;

        const int c   = lane & 15;
        const int ptg = l * 4 + (c >> 2);
        const float a  = __shfl_sync(FULLMASK, anorm, ptg);
        const float ox = __shfl_sync(FULLMASK, offv, 2 * ptg);
        const float oy = __shfl_sync(FULLMASK, offv, 2 * ptg + 1);
        const float x = (rx + ox * invW) * (float)Wl - 0.5f;
        const float y = (ry + oy * invH) * (float)Hl - 0.5f;
        const float xf = floorf(x), yf = floorf(y);
        const float lx = x - xf, ly = y - yf;
        const int xi = (int)xf + (c & 1);
        const int yi = (int)yf + ((c >> 1) & 1);
        const float wx = (c & 1) ? lx : (1.f - lx);
        const float wy = ((c >> 1) & 1) ? ly : (1.f - ly);
        const float w = a * wx * wy;
        const bool valid = (lane < 16) &&
                           ((unsigned)xi < (unsigned)Wl) &&
                           ((unsigned)yi < (unsigned)Hl);
        const int key = valid ? (yi * Wl + xi) : -1;
        const float wl = valid ? w : 0.f;
        wl_acc += wl;

        const unsigned mm = __match_any_sync(FULLMASK, key);

        float wtot = 0.f;
        #pragma unroll
        for (int j = 0; j < 16; j++) {
            const float wj = __shfl_sync(FULLMASK, wl, j);
            if ((mm >> j) & 1u) wtot += wj;
        }
        const bool leader = valid && ((int)(__ffs(mm) - 1) == lane);

        // ILP-2 gather: two distinct rows per iteration, loads batched before FMAs
        unsigned bal = __ballot_sync(FULLMASK, leader);
        while (bal) {
            const int src0 = __ffs(bal) - 1;
            bal &= bal - 1;
            if (bal) {
                const int src1 = __ffs(bal) - 1;
                bal &= bal - 1;
                const int   i0 = __shfl_sync(FULLMASK, key, src0);
                const float w0 = __shfl_sync(FULLMASK, wtot, src0);
                const int   i1 = __shfl_sync(FULLMASK, key, src1);
                const float w1 = __shfl_sync(FULLMASK, wtot, src1);
                ACCUM2(lb + (size_t)i0 * C_, w0, lb + (size_t)i1 * C_, w1);
            } else {
                const int   i0 = __shfl_sync(FULLMASK, key, src0);
                const float w0 = __shfl_sync(FULLMASK, wtot, src0);
                ACCUM1(lb + (size_t)i0 * C_, w0);
            }
        }
    }
#undef ACCUM1
#undef ACCUM2

    float wsum = wl_acc;
    #pragma unroll
    for (int o = 16; o; o >>= 1) wsum += __shfl_xor_sync(FULLMASK, wsum, o);

    bf16* ag = g_aggh + ((size_t)r * M_ + m) * C_;
    {
        bf162 p0 = __floats2bfloat162_rn(a0[0], a0[1]);
        bf162 p1 = __floats2bfloat162_rn(a0[2], a0[3]);
        uint2 u; u.x = *(uint32_t*)&p0; u.y = *(uint32_t*)&p1;
        *(uint2*)(ag + lane * 4) = u;
        p0 = __floats2bfloat162_rn(a1[0], a1[1]);
        p1 = __floats2bfloat162_rn(a1[2], a1[3]);
        u.x = *(uint32_t*)&p0; u.y = *(uint32_t*)&p1;
        *(uint2*)(ag + 128 + lane * 4) = u;
    }
    if (lane == 0) g_wsum[(size_t)r * M_ + m] = wsum;
}

// ---------------- LayerNorm: warp per row, lane holds 8 channels ----------------
__global__ __launch_bounds__(256) void ln1_kernel(
    const float* __restrict__ query,
    const float* __restrict__ lw, const float* __restrict__ lb)
{
    const int r    = blockIdx.x * 8 + (threadIdx.x >> 5);
    const int lane = threadIdx.x & 31;
    const size_t base = (size_t)r * C_ + lane * 8;

    float4 q0 = *(const float4*)&query[base];
    float4 q1 = *(const float4*)&query[base + 4];
    float4 f0 = *(const float4*)&g_feat[base];
    float4 f1 = *(const float4*)&g_feat[base + 4];
    float v[8] = {q0.x + f0.x, q0.y + f0.y, q0.z + f0.z, q0.w + f0.w,
                  q1.x + f1.x, q1.y + f1.y, q1.z + f1.z, q1.w + f1.w};

    float sum = 0.f, sq = 0.f;
    #pragma unroll
    for (int i = 0; i < 8; i++) { sum += v[i]; sq = fmaf(v[i], v[i], sq); }
    #pragma unroll
    for (int o = 16; o; o >>= 1) {
        sum += __shfl_xor_sync(FULLMASK, sum, o);
        sq  += __shfl_xor_sync(FULLMASK, sq, o);
    }
    const float mu  = sum * (1.f / 256.f);
    const float var = sq * (1.f / 256.f) - mu * mu;
    const float rs  = rsqrtf(var + 1e-6f);

    float4 w0 = *(const float4*)&lw[lane * 8];
    float4 w1 = *(const float4*)&lw[lane * 8 + 4];
    float4 b0 = *(const float4*)&lb[lane * 8];
    float4 b1 = *(const float4*)&lb[lane * 8 + 4];
    float o[8];
    o[0] = (v[0] - mu) * rs * w0.x + b0.x;
    o[1] = (v[1] - mu) * rs * w0.y + b0.y;
    o[2] = (v[2] - mu) * rs * w0.z + b0.z;
    o[3] = (v[3] - mu) * rs * w0.w + b0.w;
    o[4] = (v[4] - mu) * rs * w1.x + b1.x;
    o[5] = (v[5] - mu) * rs * w1.y + b1.y;
    o[6] = (v[6] - mu) * rs * w1.z + b1.z;
    o[7] = (v[7] - mu) * rs * w1.w + b1.w;

    float4 s0, s1;
    s0.x = o[0]; s0.y = o[1]; s0.z = o[2]; s0.w = o[3];
    s1.x = o[4]; s1.y = o[5]; s1.z = o[6]; s1.w = o[7];
    *(float4*)&g_x1[base]     = s0;
    *(float4*)&g_x1[base + 4] = s1;
    uint4 uh;
    bf162 p;
    p = __floats2bfloat162_rn(o[0], o[1]); uh.x = *(uint32_t*)&p;
    p = __floats2bfloat162_rn(o[2], o[3]); uh.y = *(uint32_t*)&p;
    p = __floats2bfloat162_rn(o[4], o[5]); uh.z = *(uint32_t*)&p;
    p = __floats2bfloat162_rn(o[6], o[7]); uh.w = *(uint32_t*)&p;
    *(uint4*)&g_x1h[base] = uh;
}

__global__ __launch_bounds__(256) void ln2_cls_kernel(
    const float* __restrict__ lw, const float* __restrict__ lb,
    const float* __restrict__ wcls, const float* __restrict__ bcls,
    float* __restrict__ out)
{
    const int r    = blockIdx.x * 8 + (threadIdx.x >> 5);
    const int lane = threadIdx.x & 31;
    const size_t base = (size_t)r * C_ + lane * 8;

    float4 q0 = *(const float4*)&g_x1[base];
    float4 q1 = *(const float4*)&g_x1[base + 4];
    float4 f0 = *(const float4*)&g_h2[base];
    float4 f1 = *(const float4*)&g_h2[base + 4];
    float v[8] = {q0.x + f0.x, q0.y + f0.y, q0.z + f0.z, q0.w + f0.w,
                  q1.x + f1.x, q1.y + f1.y, q1.z + f1.z, q1.w + f1.w};

    float sum = 0.f, sq = 0.f;
    #pragma unroll
    for (int i = 0; i < 8; i++) { sum += v[i]; sq = fmaf(v[i], v[i], sq); }
    #pragma unroll
    for (int o = 16; o; o >>= 1) {
        sum += __shfl_xor_sync(FULLMASK, sum, o);
        sq  += __shfl_xor_sync(FULLMASK, sq, o);
    }
    const float mu  = sum * (1.f / 256.f);
    const float var = sq * (1.f / 256.f) - mu * mu;
    const float rs  = rsqrtf(var + 1e-6f);

    float x2[8];
    #pragma unroll
    for (int i = 0; i < 8; i++) {
        const int ch = lane * 8 + i;
        x2[i] = (v[i] - mu) * rs * lw[ch] + lb[ch];
    }

    float pr[10];
    #pragma unroll
    for (int j = 0; j < 10; j++) pr[j] = 0.f;
    #pragma unroll
    for (int i = 0; i < 8; i++) {
        const int ch = lane * 8 + i;
        #pragma unroll
        for (int j = 0; j < 10; j++)
            pr[j] = fmaf(x2[i], wcls[ch * 10 + j], pr[j]);
    }
    #pragma unroll
    for (int o = 16; o; o >>= 1)
        #pragma unroll
        for (int j = 0; j < 10; j++) pr[j] += __shfl_xor_sync(FULLMASK, pr[j], o);

    if (lane < 10) {
        float s = bcls[lane];
        #pragma unroll
        for (int j = 0; j < 10; j++) if (lane == j) s += pr[j];
        out[(size_t)r * NC_ + lane] = s;
    }
}

// ---------------- launch ----------------
#define SMEM64 ((4*64*20 + 4*64*20) * 4)   // 40960
#define SMEM32 ((4*64*20 + 4*32*20) * 4)   // 30720

extern "C" void kernel_launch(void* const* d_in, const int* in_sizes, int n_in,
                              void* d_out, int out_size)
{
    const float* query  = (const float*)d_in[0];
    const float* value  = (const float*)d_in[1];
    const float* refp   = (const float*)d_in[2];
    const float* w_value= (const float*)d_in[3];
    const float* b_value= (const float*)d_in[4];
    const float* w_off  = (const float*)d_in[5];
    const float* b_off  = (const float*)d_in[6];
    const float* w_attn = (const float*)d_in[7];
    const float* b_attn = (const float*)d_in[8];
    const float* w_out  = (const float*)d_in[9];
    const float* b_out  = (const float*)d_in[10];
    const float* ln1w   = (const float*)d_in[11];
    const float* ln1b   = (const float*)d_in[12];
    const float* w_ffn1 = (const float*)d_in[13];
    const float* b_ffn1 = (const float*)d_in[14];
    const float* w_ffn2 = (const float*)d_in[15];
    const float* b_ffn2 = (const float*)d_in[16];
    const float* ln2w   = (const float*)d_in[17];
    const float* ln2b   = (const float*)d_in[18];
    const float* w_cls  = (const float*)d_in[19];
    const float* b_cls  = (const float*)d_in[20];
    float* out = (float*)d_out;

    float *p_qout, *p_wsum, *p_feat, *p_x1, *p_h2, *p_bq;
    bf16  *p_aggh, *p_featvh, *p_x1h, *p_hh, *p_qbf;
    bf16  *p_wqTh, *p_woutTh, *p_f1Th, *p_f2Th, *p_wvTh;
    cudaGetSymbolAddress((void**)&p_qout,   g_qout);
    cudaGetSymbolAddress((void**)&p_aggh,   g_aggh);
    cudaGetSymbolAddress((void**)&p_wsum,   g_wsum);
    cudaGetSymbolAddress((void**)&p_featvh, g_featvh);
    cudaGetSymbolAddress((void**)&p_feat,   g_feat);
    cudaGetSymbolAddress((void**)&p_x1,     g_x1);
    cudaGetSymbolAddress((void**)&p_x1h,    g_x1h);
    cudaGetSymbolAddress((void**)&p_hh,     g_hh);
    cudaGetSymbolAddress((void**)&p_h2,     g_h2);
    cudaGetSymbolAddress((void**)&p_qbf,    g_qbf);
    cudaGetSymbolAddress((void**)&p_wqTh,   g_wqTh);
    cudaGetSymbolAddress((void**)&p_bq,     g_bq);
    cudaGetSymbolAddress((void**)&p_woutTh, g_woutTh);
    cudaGetSymbolAddress((void**)&p_f1Th,   g_f1Th);
    cudaGetSymbolAddress((void**)&p_f2Th,   g_f2Th);
    cudaGetSymbolAddress((void**)&p_wvTh,   g_wvTh);

    cudaFuncSetAttribute(gemm_bf<64,0,0>, cudaFuncAttributeMaxDynamicSharedMemorySize, SMEM64);
    cudaFuncSetAttribute(gemm_bf<64,1,1>, cudaFuncAttributeMaxDynamicSharedMemorySize, SMEM64);
    cudaFuncSetAttribute(gemm_bf<32,2,1>, cudaFuncAttributeMaxDynamicSharedMemorySize, SMEM32);

    // 0. weight + query bf16 prep
    prep_weights<<<9990, 256>>>(query, w_off, w_attn, b_off, b_attn,
                                w_out, w_ffn1, w_ffn2, w_value);
    // 1. fused query projection: [off | attn] = q @ [w_off | w_attn]   grid 678
    gemm_bf<64,0,0><<<dim3(MT64, 6), 256, SMEM64>>>(p_qbf, C_, 0, p_wqTh, 256, 0, p_bq, 0,
                                                    nullptr, p_qout, 384, 0, R_, 256);
    // 2. deformable sampling + weighted aggregation (match_any dedup, ILP-2 gather)
    sample_agg_kernel<<<R_, 256>>>(value, refp);
    // 3. per-head value projection (thin GEMM N=32 per head)   grid 904
    gemm_bf<32,2,1><<<dim3(MT64, 1, M_), 256, SMEM32>>>(p_aggh, 2048, 256, p_wvTh, 256, 8192,
                                                        b_value, 32, p_wsum,
                                                        p_featvh, C_, 32, R_, 256);
    // 4. output projection (fp32 out for LN)   grid 452
    gemm_bf<64,0,0><<<dim3(MT64, 4), 256, SMEM64>>>(p_featvh, C_, 0, p_woutTh, 256, 0, b_out, 0,
                                                    nullptr, p_feat, C_, 0, R_, 256);
    // 5. residual + LN1 (warp per row)
    ln1_kernel<<<R_ / 8, 256>>>(query, ln1w, ln1b);
    // 6. FFN   grids 1808 / 452
    gemm_bf<64,1,1><<<dim3(MT64, 16), 256, SMEM64>>>(p_x1h, C_, 0, p_f1Th, 256, 0, b_ffn1, 0,
                                                     nullptr, p_hh, FFN_, 0, R_, 256);
    gemm_bf<64,0,0><<<dim3(MT64, 4), 256, SMEM64>>>(p_hh, FFN_, 0, p_f2Th, 1024, 0, b_ffn2, 0,
                                                    nullptr, p_h2, C_, 0, R_, 1024);
    // 7. residual + LN2 + classifier (warp per row)
    ln2_cls_kernel<<<R_ / 8, 256>>>(ln2w, ln2b, w_cls, b_cls, out);
}

// round 15
// speedup vs baseline: 1.0445x; 1.0055x over previous
#include <cuda_runtime.h>
#include <cuda_bf16.h>
#include <math.h>
#include <stdint.h>

#define FULLMASK 0xffffffffu

// Problem constants
#define B_    8
#define NQ_   900
#define C_    256
#define M_    8
#define D_    32
#define S_    19560
#define FFN_  1024
#define NC_   10
#define R_    (B_*NQ_)            // 7200 rows
#define MT64  ((R_ + 63) / 64)    // 113 M tiles (BM=64)

typedef __nv_bfloat16  bf16;
typedef __nv_bfloat162 bf162;

// ---------------- scratch (static device globals) ----------------
__device__ float g_qout [R_ * 384];        // [off(256) | attn(128)] per row (fp32)
__device__ bf16  g_aggh [R_ * M_ * C_];    // aggregated value rows, bf16
__device__ float g_wsum [R_ * M_];
__device__ bf16  g_featvh[R_ * C_];        // per-head projected features, bf16
__device__ float g_feat [R_ * C_];         // after w_out (fp32, LN input)
__device__ float g_x1   [R_ * C_];         // after LN1 (fp32, residual)
__device__ bf16  g_x1h  [R_ * C_];         // after LN1 (bf16, ffn1 input)
__device__ bf16  g_hh   [R_ * FFN_];       // FFN hidden, bf16
__device__ float g_h2   [R_ * C_];         // after w_ffn2 (fp32)
// bf16 weights [N, K] + bf16 query
__device__ bf16  g_qbf  [R_ * C_];
__device__ bf16  g_wqTh [384 * 256];
__device__ float g_bq   [384];
__device__ bf16  g_woutTh[256 * 256];
__device__ bf16  g_f1Th [1024 * 256];
__device__ bf16  g_f2Th [256 * 1024];
__device__ bf16  g_wvTh [M_ * D_ * 256];   // per-head value-proj slice [8][32][256]

// bf16 m16n8k16 warp MMA
#define MMA_BF16(c, a, b) \
    asm volatile("mma.sync.aligned.m16n8k16.row.col.f32.bf16.bf16.f32 " \
        "{%0,%1,%2,%3}, {%4,%5,%6,%7}, {%8,%9}, {%0,%1,%2,%3};" \
        : "+f"((c)[0]), "+f"((c)[1]), "+f"((c)[2]), "+f"((c)[3]) \
        : "r"((a)[0]), "r"((a)[1]), "r"((a)[2]), "r"((a)[3]), \
          "r"((b)[0]), "r"((b)[1]))

__device__ __forceinline__ void ldsm_x4(uint32_t& r0, uint32_t& r1, uint32_t& r2,
                                        uint32_t& r3, const void* p) {
    uint32_t a = (uint32_t)__cvta_generic_to_shared(p);
    asm volatile("ldmatrix.sync.aligned.m8n8.x4.shared.b16 {%0,%1,%2,%3}, [%4];"
                 : "=r"(r0), "=r"(r1), "=r"(r2), "=r"(r3) : "r"(a));
}
__device__ __forceinline__ void ldsm_x2(uint32_t& r0, uint32_t& r1, const void* p) {
    uint32_t a = (uint32_t)__cvta_generic_to_shared(p);
    asm volatile("ldmatrix.sync.aligned.m8n8.x2.shared.b16 {%0,%1}, [%2];"
                 : "=r"(r0), "=r"(r1) : "r"(a));
}

#define CP_ASYNC16(saddr, gaddr, srcsz) \
    asm volatile("cp.async.cg.shared.global [%0], [%1], 16, %2;" \
        :: "r"(saddr), "l"(gaddr), "r"(srcsz))
#define CP_COMMIT()  asm volatile("cp.async.commit_group;" ::: "memory")
#define CP_WAIT2()   asm volatile("cp.async.wait_group 2;" ::: "memory")

// ---------------- weight / activation prep (all bf16 conversions) ----------------
__global__ __launch_bounds__(256) void prep_weights(
    const float* __restrict__ query,
    const float* __restrict__ w_off, const float* __restrict__ w_attn,
    const float* __restrict__ b_off, const float* __restrict__ b_attn,
    const float* __restrict__ w_out_, const float* __restrict__ w_ffn1,
    const float* __restrict__ w_ffn2, const float* __restrict__ w_value)
{
    int idx = blockIdx.x * 256 + threadIdx.x;
    if (idx < 98304) {                                   // wqTh [384,256]
        int n = idx >> 8, k = idx & 255;
        g_wqTh[idx] = __float2bfloat16_rn((n < 256) ? w_off[k * 256 + n]
                                                    : w_attn[k * 128 + (n - 256)]);
        if (idx < 384) g_bq[idx] = (idx < 256) ? b_off[idx] : b_attn[idx - 256];
        return;
    }
    idx -= 98304;
    if (idx < 65536) {                                   // woutTh [256,256]
        int n = idx >> 8, k = idx & 255;
        g_woutTh[idx] = __float2bfloat16_rn(w_out_[k * 256 + n]);
        return;
    }
    idx -= 65536;
    if (idx < 262144) {                                  // f1Th [1024,256]
        int n = idx >> 8, k = idx & 255;
        g_f1Th[idx] = __float2bfloat16_rn(w_ffn1[k * 1024 + n]);
        return;
    }
    idx -= 262144;
    if (idx < 262144) {                                  // f2Th [256,1024]
        int n = idx >> 10, k = idx & 1023;
        g_f2Th[idx] = __float2bfloat16_rn(w_ffn2[k * 256 + n]);
        return;
    }
    idx -= 262144;
    if (idx < 65536) {                                   // wvTh [8][32][256]
        int m = idx >> 13, n = (idx >> 8) & 31, k = idx & 255;
        g_wvTh[idx] = __float2bfloat16_rn(w_value[k * 256 + m * 32 + n]);
        return;
    }
    idx -= 65536;
    if (idx < R_ * C_ / 4) {                             // qbf (float4 -> 4 bf16)
        float4 v = *(const float4*)&query[idx * 4];
        bf162 p0 = __floats2bfloat162_rn(v.x, v.y);
        bf162 p1 = __floats2bfloat162_rn(v.z, v.w);
        uint2 u;
        u.x = *(uint32_t*)&p0; u.y = *(uint32_t*)&p1;
        *(uint2*)&g_qbf[idx * 4] = u;
        return;
    }
}

// ---------------- bf16 mma GEMM: BM=64, ldmatrix + 4-stage cp.async ----------------
// (identical to the 219.2us round-12 kernel)
template<int BN, int EPI, int OBF>
__global__ __launch_bounds__(256) void gemm_bf(
    const bf16* __restrict__ A, int lda, int zA,
    const bf16* __restrict__ WT, int ldb, int zB,
    const float* __restrict__ bias, int zbias,
    const float* __restrict__ wsum,
    void* __restrict__ Cg, int ldc, int zC,
    int Mrows, int Klen)
{
    constexpr int WN = BN / 4;
    constexpr int NJ = WN / 8;
    extern __shared__ float smp[];
    float* As = smp;                    // [4][64][20]
    float* Bs = smp + 4 * 64 * 20;      // [4][BN][20]
#define ASA(s,r,c) As[(((s) << 6) + (r)) * 20 + (c)]
#define BSA(s,r,c) Bs[((s) * BN + (r)) * 20 + (c)]

    const int tid  = threadIdx.x;
    const int wid  = tid >> 5, lane = tid & 31;
    const int g    = lane >> 2, tg = lane & 3;
    const int wm   = (wid & 1) << 5;
    const int wn   = (wid >> 1) * WN;
    const int m0   = blockIdx.x * 64;
    const int n0   = blockIdx.y * BN;
    const int z    = blockIdx.z;

    A    += (size_t)z * zA;
    WT   += (size_t)z * zB;
    bias += z * zbias;

    const int ar  = tid >> 2;
    const int aw  = (tid & 3) << 2;
    const int br  = tid >> 2;
    const int bw  = (tid & 3) << 2;
    const uint32_t aval = ((m0 + ar) < Mrows) ? 16u : 0u;
    const bool bldr = (BN == 64) || (tid < 128);
    const bf16* agp = A  + (size_t)(m0 + ar) * lda + (aw << 1);
    const bf16* bgp = WT + (size_t)(n0 + br) * ldb + (bw << 1);

    const int a_lm_row = wm + (lane & 15);
    const int a_lm_col = (lane >> 4) << 2;
    const int b_lm_row = (BN == 64) ? (wn + ((lane >> 4) << 3) + (lane & 7))
                                    : (wn + (lane & 7));
    const int b_lm_col = ((lane >> 3) & 1) << 2;

    const int niter = Klen >> 5;

    auto issue = [&](int kb, int s) {
        uint32_t sa = (uint32_t)__cvta_generic_to_shared(&ASA(s, ar, aw));
        CP_ASYNC16(sa, agp + (kb << 5), aval);
        if (bldr) {
            uint32_t sb = (uint32_t)__cvta_generic_to_shared(&BSA(s, br, bw));
            CP_ASYNC16(sb, bgp + (kb << 5), 16u);
        }
    };

    float acc[2][NJ][4];
    #pragma unroll
    for (int i = 0; i < 2; i++)
        #pragma unroll
        for (int j = 0; j < NJ; j++)
            #pragma unroll
            for (int v = 0; v < 4; v++) acc[i][j][v] = 0.f;

    issue(0, 0); CP_COMMIT();
    issue(1, 1); CP_COMMIT();
    issue(2, 2); CP_COMMIT();

    for (int it = 0; it < niter; it++) {
        const int s = it & 3;
        CP_WAIT2();
        __syncthreads();
        if (it + 3 < niter) issue(it + 3, (it + 3) & 3);
        CP_COMMIT();

        uint32_t af[2][2][4];
        uint32_t bfr[2][NJ][2];
        #pragma unroll
        for (int kq = 0; kq < 2; kq++) {
            const int ks = kq << 3;
            #pragma unroll
            for (int mi = 0; mi < 2; mi++)
                ldsm_x4(af[kq][mi][0], af[kq][mi][1], af[kq][mi][2], af[kq][mi][3],
                        &ASA(s, a_lm_row + (mi << 4), ks + a_lm_col));
            if (BN == 64) {
                uint32_t r0, r1, r2, r3;
                ldsm_x4(r0, r1, r2, r3, &BSA(s, b_lm_row, ks + b_lm_col));
                bfr[kq][0][0] = r0; bfr[kq][0][1] = r1;
                if (NJ > 1) { bfr[kq][NJ - 1][0] = r2; bfr[kq][NJ - 1][1] = r3; }
            } else {
                ldsm_x2(bfr[kq][0][0], bfr[kq][0][1], &BSA(s, b_lm_row, ks + b_lm_col));
            }
        }
        #pragma unroll
        for (int kq = 0; kq < 2; kq++)
            #pragma unroll
            for (int mi = 0; mi < 2; mi++)
                #pragma unroll
                for (int nj = 0; nj < NJ; nj++)
                    MMA_BF16(acc[mi][nj], af[kq][mi], bfr[kq][nj]);
    }

    #pragma unroll
    for (int nj = 0; nj < NJ; nj++) {
        const int cloc = n0 + wn + (nj << 3) + (tg << 1);
        const int col  = cloc + z * zC;
        const float2 bv = *(const float2*)&bias[cloc];
        #pragma unroll
        for (int mi = 0; mi < 2; mi++) {
            const int row0 = m0 + wm + (mi << 4) + g;
            const int row1 = row0 + 8;
            float2 v0 = make_float2(acc[mi][nj][0], acc[mi][nj][1]);
            float2 v1 = make_float2(acc[mi][nj][2], acc[mi][nj][3]);
            if (EPI == 0) {
                v0.x += bv.x; v0.y += bv.y; v1.x += bv.x; v1.y += bv.y;
            } else if (EPI == 1) {
                v0.x = fmaxf(v0.x + bv.x, 0.f); v0.y = fmaxf(v0.y + bv.y, 0.f);
                v1.x = fmaxf(v1.x + bv.x, 0.f); v1.y = fmaxf(v1.y + bv.y, 0.f);
            }
            if (row0 < Mrows) {
                if (EPI == 2) {
                    const float ws = wsum[(size_t)row0 * 8 + z];
                    v0.x += ws * bv.x; v0.y += ws * bv.y;
                }
                if (OBF) {
                    bf162 p = __floats2bfloat162_rn(v0.x, v0.y);
                    *(bf162*)((bf16*)Cg + (size_t)row0 * ldc + col) = p;
                } else {
                    *(float2*)((float*)Cg + (size_t)row0 * ldc + col) = v0;
                }
            }
            if (row1 < Mrows) {
                if (EPI == 2) {
                    const float ws = wsum[(size_t)row1 * 8 + z];
                    v1.x += ws * bv.x; v1.y += ws * bv.y;
                }
                if (OBF) {
                    bf162 p = __floats2bfloat162_rn(v1.x, v1.y);
                    *(bf162*)((bf16*)Cg + (size_t)row1 * ldc + col) = p;
                } else {
                    *(float2*)((float*)Cg + (size_t)row1 * ldc + col) = v1;
                }
            }
        }
    }
#undef ASA
#undef BSA
}

// ---------------- deformable sampling + aggregation (exact R12 form) ----------------
__global__ __launch_bounds__(256) void sample_agg_kernel(
    const float* __restrict__ value, const float* __restrict__ ref_points)
{
    const int r    = blockIdx.x;
    const int b    = r / NQ_;
    const int m    = threadIdx.x >> 5;
    const int lane = threadIdx.x & 31;

    const float rx = ref_points[r * 2 + 0];
    const float ry = ref_points[r * 2 + 1];

    float araw = (lane < 16) ? g_qout[(size_t)r * 384 + 256 + m * 16 + lane] : -1e30f;
    float amax = araw;
    #pragma unroll
    for (int o = 8; o; o >>= 1) amax = fmaxf(amax, __shfl_xor_sync(FULLMASK, amax, o, 16));
    float e = (lane < 16) ? __expf(araw - amax) : 0.f;
    float es = e;
    #pragma unroll
    for (int o = 8; o; o >>= 1) es += __shfl_xor_sync(FULLMASK, es, o, 16);
    const float anorm = e / es;

    const float offv = g_qout[(size_t)r * 384 + m * 32 + lane];

    float a0[4] = {0.f, 0.f, 0.f, 0.f};
    float a1[4] = {0.f, 0.f, 0.f, 0.f};
    float wl_acc = 0.f;

    const int Hs[4]  = {92, 46, 23, 12};
    const int Wls[4] = {160, 80, 40, 20};
    const int St[4]  = {0, 14720, 18400, 19320};
    const float* vb = value + (size_t)b * S_ * C_;

#define ACCUM(ptr, wgt) do {                                          \
        const float4* _p4 = (const float4*)(ptr);                     \
        float4 _v0 = _p4[lane];                                       \
        float4 _v1 = _p4[32 + lane];                                  \
        a0[0] = fmaf(wgt, _v0.x, a0[0]);                              \
        a0[1] = fmaf(wgt, _v0.y, a0[1]);                              \
        a0[2] = fmaf(wgt, _v0.z, a0[2]);                              \
        a0[3] = fmaf(wgt, _v0.w, a0[3]);                              \
        a1[0] = fmaf(wgt, _v1.x, a1[0]);                              \
        a1[1] = fmaf(wgt, _v1.y, a1[1]);                              \
        a1[2] = fmaf(wgt, _v1.z, a1[2]);                              \
        a1[3] = fmaf(wgt, _v1.w, a1[3]);                              \
    } while (0)

    #pragma unroll
    for (int l = 0; l < 4; l++) {
        const int Hl = Hs[l], Wl = Wls[l];
        const float invW = 1.f / (float)Wl, invH = 1.f / (float)Hl;
        const float* lb = vb + (size_t)St[l] * C_;

        const int c   = lane & 15;
        const int ptg = l * 4 + (c >> 2);
        const float a  = __shfl_sync(FULLMASK, anorm, ptg);
        const float ox = __shfl_sync(FULLMASK, offv, 2 * ptg);
        const float oy = __shfl_sync(FULLMASK, offv, 2 * ptg + 1);
        const float x = (rx + ox * invW) * (float)Wl - 0.5f;
        const float y = (ry + oy * invH) * (float)Hl - 0.5f;
        const float xf = floorf(x), yf = floorf(y);
        const float lx = x - xf, ly = y - yf;
        const int xi = (int)xf + (c & 1);
        const int yi = (int)yf + ((c >> 1) & 1);
        const float wx = (c & 1) ? lx : (1.f - lx);
        const float wy = ((c >> 1) & 1) ? ly : (1.f - ly);
        const float w = a * wx * wy;
        const bool valid = (lane < 16) &&
                           ((unsigned)xi < (unsigned)Wl) &&
                           ((unsigned)yi < (unsigned)Hl);
        const int key = valid ? (yi * Wl + xi) : -1;
        const float wl = valid ? w : 0.f;
        wl_acc += wl;

        const unsigned mm = __match_any_sync(FULLMASK, key);

        float wtot = 0.f;
        #pragma unroll
        for (int j = 0; j < 16; j++) {
            const float wj = __shfl_sync(FULLMASK, wl, j);
            if ((mm >> j) & 1u) wtot += wj;
        }
        const bool leader = valid && ((int)(__ffs(mm) - 1) == lane);

        unsigned bal = __ballot_sync(FULLMASK, leader);
        while (bal) {
            const int src = __ffs(bal) - 1;
            bal &= bal - 1;
            const int   idx = __shfl_sync(FULLMASK, key, src);
            const float wt  = __shfl_sync(FULLMASK, wtot, src);
            ACCUM(lb + (size_t)idx * C_, wt);
        }
    }
#undef ACCUM

    float wsum = wl_acc;
    #pragma unroll
    for (int o = 16; o; o >>= 1) wsum += __shfl_xor_sync(FULLMASK, wsum, o);

    bf16* ag = g_aggh + ((size_t)r * M_ + m) * C_;
    {
        bf162 p0 = __floats2bfloat162_rn(a0[0], a0[1]);
        bf162 p1 = __floats2bfloat162_rn(a0[2], a0[3]);
        uint2 u; u.x = *(uint32_t*)&p0; u.y = *(uint32_t*)&p1;
        *(uint2*)(ag + lane * 4) = u;
        p0 = __floats2bfloat162_rn(a1[0], a1[1]);
        p1 = __floats2bfloat162_rn(a1[2], a1[3]);
        u.x = *(uint32_t*)&p0; u.y = *(uint32_t*)&p1;
        *(uint2*)(ag + 128 + lane * 4) = u;
    }
    if (lane == 0) g_wsum[(size_t)r * M_ + m] = wsum;
}

// ---------------- LayerNorm: warp per row, lane holds 8 channels ----------------
__global__ __launch_bounds__(256) void ln1_kernel(
    const float* __restrict__ query,
    const float* __restrict__ lw, const float* __restrict__ lb)
{
    const int r    = blockIdx.x * 8 + (threadIdx.x >> 5);
    const int lane = threadIdx.x & 31;
    const size_t base = (size_t)r * C_ + lane * 8;

    float4 q0 = *(const float4*)&query[base];
    float4 q1 = *(const float4*)&query[base + 4];
    float4 f0 = *(const float4*)&g_feat[base];
    float4 f1 = *(const float4*)&g_feat[base + 4];
    float v[8] = {q0.x + f0.x, q0.y + f0.y, q0.z + f0.z, q0.w + f0.w,
                  q1.x + f1.x, q1.y + f1.y, q1.z + f1.z, q1.w + f1.w};

    float sum = 0.f, sq = 0.f;
    #pragma unroll
    for (int i = 0; i < 8; i++) { sum += v[i]; sq = fmaf(v[i], v[i], sq); }
    #pragma unroll
    for (int o = 16; o; o >>= 1) {
        sum += __shfl_xor_sync(FULLMASK, sum, o);
        sq  += __shfl_xor_sync(FULLMASK, sq, o);
    }
    const float mu  = sum * (1.f / 256.f);
    const float var = sq * (1.f / 256.f) - mu * mu;
    const float rs  = rsqrtf(var + 1e-6f);

    float4 w0 = *(const float4*)&lw[lane * 8];
    float4 w1 = *(const float4*)&lw[lane * 8 + 4];
    float4 b0 = *(const float4*)&lb[lane * 8];
    float4 b1 = *(const float4*)&lb[lane * 8 + 4];
    float o[8];
    o[0] = (v[0] - mu) * rs * w0.x + b0.x;
    o[1] = (v[1] - mu) * rs * w0.y + b0.y;
    o[2] = (v[2] - mu) * rs * w0.z + b0.z;
    o[3] = (v[3] - mu) * rs * w0.w + b0.w;
    o[4] = (v[4] - mu) * rs * w1.x + b1.x;
    o[5] = (v[5] - mu) * rs * w1.y + b1.y;
    o[6] = (v[6] - mu) * rs * w1.z + b1.z;
    o[7] = (v[7] - mu) * rs * w1.w + b1.w;

    float4 s0, s1;
    s0.x = o[0]; s0.y = o[1]; s0.z = o[2]; s0.w = o[3];
    s1.x = o[4]; s1.y = o[5]; s1.z = o[6]; s1.w = o[7];
    *(float4*)&g_x1[base]     = s0;
    *(float4*)&g_x1[base + 4] = s1;
    uint4 uh;
    bf162 p;
    p = __floats2bfloat162_rn(o[0], o[1]); uh.x = *(uint32_t*)&p;
    p = __floats2bfloat162_rn(o[2], o[3]); uh.y = *(uint32_t*)&p;
    p = __floats2bfloat162_rn(o[4], o[5]); uh.z = *(uint32_t*)&p;
    p = __floats2bfloat162_rn(o[6], o[7]); uh.w = *(uint32_t*)&p;
    *(uint4*)&g_x1h[base] = uh;
}

__global__ __launch_bounds__(256) void ln2_cls_kernel(
    const float* __restrict__ lw, const float* __restrict__ lb,
    const float* __restrict__ wcls, const float* __restrict__ bcls,
    float* __restrict__ out)
{
    const int r    = blockIdx.x * 8 + (threadIdx.x >> 5);
    const int lane = threadIdx.x & 31;
    const size_t base = (size_t)r * C_ + lane * 8;

    float4 q0 = *(const float4*)&g_x1[base];
    float4 q1 = *(const float4*)&g_x1[base + 4];
    float4 f0 = *(const float4*)&g_h2[base];
    float4 f1 = *(const float4*)&g_h2[base + 4];
    float v[8] = {q0.x + f0.x, q0.y + f0.y, q0.z + f0.z, q0.w + f0.w,
                  q1.x + f1.x, q1.y + f1.y, q1.z + f1.z, q1.w + f1.w};

    float sum = 0.f, sq = 0.f;
    #pragma unroll
    for (int i = 0; i < 8; i++) { sum += v[i]; sq = fmaf(v[i], v[i], sq); }
    #pragma unroll
    for (int o = 16; o; o >>= 1) {
        sum += __shfl_xor_sync(FULLMASK, sum, o);
        sq  += __shfl_xor_sync(FULLMASK, sq, o);
    }
    const float mu  = sum * (1.f / 256.f);
    const float var = sq * (1.f / 256.f) - mu * mu;
    const float rs  = rsqrtf(var + 1e-6f);

    float x2[8];
    #pragma unroll
    for (int i = 0; i < 8; i++) {
        const int ch = lane * 8 + i;
        x2[i] = (v[i] - mu) * rs * lw[ch] + lb[ch];
    }

    float pr[10];
    #pragma unroll
    for (int j = 0; j < 10; j++) pr[j] = 0.f;
    #pragma unroll
    for (int i = 0; i < 8; i++) {
        const int ch = lane * 8 + i;
        #pragma unroll
        for (int j = 0; j < 10; j++)
            pr[j] = fmaf(x2[i], wcls[ch * 10 + j], pr[j]);
    }
    #pragma unroll
    for (int o = 16; o; o >>= 1)
        #pragma unroll
        for (int j = 0; j < 10; j++) pr[j] += __shfl_xor_sync(FULLMASK, pr[j], o);

    if (lane < 10) {
        float s = bcls[lane];
        #pragma unroll
        for (int j = 0; j < 10; j++) if (lane == j) s += pr[j];
        out[(size_t)r * NC_ + lane] = s;
    }
}

// ---------------- launch ----------------
#define SMEM64 ((4*64*20 + 4*64*20) * 4)   // 40960
#define SMEM32 ((4*64*20 + 4*32*20) * 4)   // 30720
#define PREP_BLOCKS ((98304 + 65536 + 262144 + 262144 + 65536 + R_*C_/4 + 255) / 256)

extern "C" void kernel_launch(void* const* d_in, const int* in_sizes, int n_in,
                              void* d_out, int out_size)
{
    const float* query  = (const float*)d_in[0];
    const float* value  = (const float*)d_in[1];
    const float* refp   = (const float*)d_in[2];
    const float* w_value= (const float*)d_in[3];
    const float* b_value= (const float*)d_in[4];
    const float* w_off  = (const float*)d_in[5];
    const float* b_off  = (const float*)d_in[6];
    const float* w_attn = (const float*)d_in[7];
    const float* b_attn = (const float*)d_in[8];
    const float* w_out  = (const float*)d_in[9];
    const float* b_out  = (const float*)d_in[10];
    const float* ln1w   = (const float*)d_in[11];
    const float* ln1b   = (const float*)d_in[12];
    const float* w_ffn1 = (const float*)d_in[13];
    const float* b_ffn1 = (const float*)d_in[14];
    const float* w_ffn2 = (const float*)d_in[15];
    const float* b_ffn2 = (const float*)d_in[16];
    const float* ln2w   = (const float*)d_in[17];
    const float* ln2b   = (const float*)d_in[18];
    const float* w_cls  = (const float*)d_in[19];
    const float* b_cls  = (const float*)d_in[20];
    float* out = (float*)d_out;

    float *p_qout, *p_wsum, *p_feat, *p_x1, *p_h2, *p_bq;
    bf16  *p_aggh, *p_featvh, *p_x1h, *p_hh, *p_qbf;
    bf16  *p_wqTh, *p_woutTh, *p_f1Th, *p_f2Th, *p_wvTh;
    cudaGetSymbolAddress((void**)&p_qout,   g_qout);
    cudaGetSymbolAddress((void**)&p_aggh,   g_aggh);
    cudaGetSymbolAddress((void**)&p_wsum,   g_wsum);
    cudaGetSymbolAddress((void**)&p_featvh, g_featvh);
    cudaGetSymbolAddress((void**)&p_feat,   g_feat);
    cudaGetSymbolAddress((void**)&p_x1,     g_x1);
    cudaGetSymbolAddress((void**)&p_x1h,    g_x1h);
    cudaGetSymbolAddress((void**)&p_hh,     g_hh);
    cudaGetSymbolAddress((void**)&p_h2,     g_h2);
    cudaGetSymbolAddress((void**)&p_qbf,    g_qbf);
    cudaGetSymbolAddress((void**)&p_wqTh,   g_wqTh);
    cudaGetSymbolAddress((void**)&p_bq,     g_bq);
    cudaGetSymbolAddress((void**)&p_woutTh, g_woutTh);
    cudaGetSymbolAddress((void**)&p_f1Th,   g_f1Th);
    cudaGetSymbolAddress((void**)&p_f2Th,   g_f2Th);
    cudaGetSymbolAddress((void**)&p_wvTh,   g_wvTh);

    cudaFuncSetAttribute(gemm_bf<64,0,0>, cudaFuncAttributeMaxDynamicSharedMemorySize, SMEM64);
    cudaFuncSetAttribute(gemm_bf<64,1,1>, cudaFuncAttributeMaxDynamicSharedMemorySize, SMEM64);
    cudaFuncSetAttribute(gemm_bf<32,2,1>, cudaFuncAttributeMaxDynamicSharedMemorySize, SMEM32);

    // 0. weight + query bf16 prep (exact grid)
    prep_weights<<<PREP_BLOCKS, 256>>>(query, w_off, w_attn, b_off, b_attn,
                                       w_out, w_ffn1, w_ffn2, w_value);
    // 1. fused query projection: [off | attn] = q @ [w_off | w_attn]   grid 678
    gemm_bf<64,0,0><<<dim3(MT64, 6), 256, SMEM64>>>(p_qbf, C_, 0, p_wqTh, 256, 0, p_bq, 0,
                                                    nullptr, p_qout, 384, 0, R_, 256);
    // 2. deformable sampling + weighted aggregation (R12 form)
    sample_agg_kernel<<<R_, 256>>>(value, refp);
    // 3. per-head value projection (thin GEMM N=32 per head)   grid 904
    gemm_bf<32,2,1><<<dim3(MT64, 1, M_), 256, SMEM32>>>(p_aggh, 2048, 256, p_wvTh, 256, 8192,
                                                        b_value, 32, p_wsum,
                                                        p_featvh, C_, 32, R_, 256);
    // 4. output projection (fp32 out for LN)   grid 452
    gemm_bf<64,0,0><<<dim3(MT64, 4), 256, SMEM64>>>(p_featvh, C_, 0, p_woutTh, 256, 0, b_out, 0,
                                                    nullptr, p_feat, C_, 0, R_, 256);
    // 5. residual + LN1 (warp per row)
    ln1_kernel<<<R_ / 8, 256>>>(query, ln1w, ln1b);
    // 6. FFN   grids 1808 / 452
    gemm_bf<64,1,1><<<dim3(MT64, 16), 256, SMEM64>>>(p_x1h, C_, 0, p_f1Th, 256, 0, b_ffn1, 0,
                                                     nullptr, p_hh, FFN_, 0, R_, 256);
    gemm_bf<64,0,0><<<dim3(MT64, 4), 256, SMEM64>>>(p_hh, FFN_, 0, p_f2Th, 1024, 0, b_ffn2, 0,
                                                    nullptr, p_h2, C_, 0, R_, 1024);
    // 7. residual + LN2 + classifier (warp per row)
    ln2_cls_kernel<<<R_ / 8, 256>>>(ln2w, ln2b, w_cls, b_cls, out);
}

// round 16
// speedup vs baseline: 1.0752x; 1.0295x over previous
#include <cuda_runtime.h>
#include <cuda_bf16.h>
#include <math.h>
#include <stdint.h>

#define FULLMASK 0xffffffffu

// Problem constants
#define B_    8
#define NQ_   900
#define C_    256
#define M_    8
#define D_    32
#define S_    19560
#define FFN_  1024
#define NC_   10
#define R_    (B_*NQ_)            // 7200 rows
#define MT64  ((R_ + 63) / 64)    // 113 M tiles (BM=64)

typedef __nv_bfloat16  bf16;
typedef __nv_bfloat162 bf162;

// ---------------- scratch (static device globals) ----------------
__device__ float g_qout [R_ * 384];        // [off(256) | attn(128)] per row (fp32)
__device__ bf16  g_aggh [R_ * M_ * C_];    // aggregated value rows, bf16
__device__ float g_wsum [R_ * M_];
__device__ bf16  g_featvh[R_ * C_];        // per-head projected features, bf16
__device__ float g_feat [R_ * C_];         // after w_out (fp32, LN input)
__device__ float g_x1   [R_ * C_];         // after LN1 (fp32, residual)
__device__ bf16  g_x1h  [R_ * C_];         // after LN1 (bf16, ffn1 input)
__device__ bf16  g_hh   [R_ * FFN_];       // FFN hidden, bf16
__device__ float g_h2   [R_ * C_];         // after w_ffn2 (fp32)
// bf16 weights [N, K] + bf16 query
__device__ bf16  g_qbf  [R_ * C_];
__device__ bf16  g_wqTh [384 * 256];
__device__ float g_bq   [384];
__device__ bf16  g_woutTh[256 * 256];
__device__ bf16  g_f1Th [1024 * 256];
__device__ bf16  g_f2Th [256 * 1024];
__device__ bf16  g_wvTh [M_ * D_ * 256];   // per-head value-proj slice [8][32][256]

// bf16 m16n8k16 warp MMA
#define MMA_BF16(c, a, b) \
    asm volatile("mma.sync.aligned.m16n8k16.row.col.f32.bf16.bf16.f32 " \
        "{%0,%1,%2,%3}, {%4,%5,%6,%7}, {%8,%9}, {%0,%1,%2,%3};" \
        : "+f"((c)[0]), "+f"((c)[1]), "+f"((c)[2]), "+f"((c)[3]) \
        : "r"((a)[0]), "r"((a)[1]), "r"((a)[2]), "r"((a)[3]), \
          "r"((b)[0]), "r"((b)[1]))

__device__ __forceinline__ void ldsm_x4(uint32_t& r0, uint32_t& r1, uint32_t& r2,
                                        uint32_t& r3, const void* p) {
    uint32_t a = (uint32_t)__cvta_generic_to_shared(p);
    asm volatile("ldmatrix.sync.aligned.m8n8.x4.shared.b16 {%0,%1,%2,%3}, [%4];"
                 : "=r"(r0), "=r"(r1), "=r"(r2), "=r"(r3) : "r"(a));
}
__device__ __forceinline__ void ldsm_x2(uint32_t& r0, uint32_t& r1, const void* p) {
    uint32_t a = (uint32_t)__cvta_generic_to_shared(p);
    asm volatile("ldmatrix.sync.aligned.m8n8.x2.shared.b16 {%0,%1}, [%2];"
                 : "=r"(r0), "=r"(r1) : "r"(a));
}

#define CP_ASYNC16(saddr, gaddr, srcsz) \
    asm volatile("cp.async.cg.shared.global [%0], [%1], 16, %2;" \
        :: "r"(saddr), "l"(gaddr), "r"(srcsz))
#define CP_COMMIT()  asm volatile("cp.async.commit_group;" ::: "memory")
#define CP_WAIT1()   asm volatile("cp.async.wait_group 1;" ::: "memory")

// ---------------- weight / activation prep (all bf16 conversions) ----------------
__global__ __launch_bounds__(256) void prep_weights(
    const float* __restrict__ query,
    const float* __restrict__ w_off, const float* __restrict__ w_attn,
    const float* __restrict__ b_off, const float* __restrict__ b_attn,
    const float* __restrict__ w_out_, const float* __restrict__ w_ffn1,
    const float* __restrict__ w_ffn2, const float* __restrict__ w_value)
{
    int idx = blockIdx.x * 256 + threadIdx.x;
    if (idx < 98304) {                                   // wqTh [384,256]
        int n = idx >> 8, k = idx & 255;
        g_wqTh[idx] = __float2bfloat16_rn((n < 256) ? w_off[k * 256 + n]
                                                    : w_attn[k * 128 + (n - 256)]);
        if (idx < 384) g_bq[idx] = (idx < 256) ? b_off[idx] : b_attn[idx - 256];
        return;
    }
    idx -= 98304;
    if (idx < 65536) {                                   // woutTh [256,256]
        int n = idx >> 8, k = idx & 255;
        g_woutTh[idx] = __float2bfloat16_rn(w_out_[k * 256 + n]);
        return;
    }
    idx -= 65536;
    if (idx < 262144) {                                  // f1Th [1024,256]
        int n = idx >> 8, k = idx & 255;
        g_f1Th[idx] = __float2bfloat16_rn(w_ffn1[k * 1024 + n]);
        return;
    }
    idx -= 262144;
    if (idx < 262144) {                                  // f2Th [256,1024]
        int n = idx >> 10, k = idx & 1023;
        g_f2Th[idx] = __float2bfloat16_rn(w_ffn2[k * 256 + n]);
        return;
    }
    idx -= 262144;
    if (idx < 65536) {                                   // wvTh [8][32][256]
        int m = idx >> 13, n = (idx >> 8) & 31, k = idx & 255;
        g_wvTh[idx] = __float2bfloat16_rn(w_value[k * 256 + m * 32 + n]);
        return;
    }
    idx -= 65536;
    if (idx < R_ * C_ / 4) {                             // qbf (float4 -> 4 bf16)
        float4 v = *(const float4*)&query[idx * 4];
        bf162 p0 = __floats2bfloat162_rn(v.x, v.y);
        bf162 p1 = __floats2bfloat162_rn(v.z, v.w);
        uint2 u;
        u.x = *(uint32_t*)&p0; u.y = *(uint32_t*)&p1;
        *(uint2*)&g_qbf[idx * 4] = u;
        return;
    }
}

// ---------------- bf16 mma GEMM: BM=64, K=64 per stage, 3-stage cp.async ----------------
// 256 threads, 8 warps as 2(M) x 4(N); warp tile 32 x (BN/4).
// EPI: 0 = +bias, 1 = relu(+bias), 2 = +wsum[row, z]*bias
// OBF: 1 = store bf16 output, 0 = fp32
template<int BN, int EPI, int OBF>
__global__ __launch_bounds__(256) void gemm_bf(
    const bf16* __restrict__ A, int lda, int zA,
    const bf16* __restrict__ WT, int ldb, int zB,
    const float* __restrict__ bias, int zbias,
    const float* __restrict__ wsum,
    void* __restrict__ Cg, int ldc, int zC,
    int Mrows, int Klen)
{
    constexpr int WN = BN / 4;       // 16 (BN=64) or 8 (BN=32)
    constexpr int NJ = WN / 8;       // 2 or 1
    extern __shared__ float smp[];
    float* As = smp;                      // [3][64][36] words (64 bf16 pairs? 32 used + 4 pad)
    float* Bs = smp + 3 * 64 * 36;        // [3][BN][36]
#define ASA(s,r,c) As[(((s) << 6) + (r)) * 36 + (c)]
#define BSA(s,r,c) Bs[((s) * BN + (r)) * 36 + (c)]

    const int tid  = threadIdx.x;
    const int wid  = tid >> 5, lane = tid & 31;
    const int g    = lane >> 2, tg = lane & 3;
    const int wm   = (wid & 1) << 5;     // 0 or 32
    const int wn   = (wid >> 1) * WN;    // 4 N-groups
    const int m0   = blockIdx.x * 64;
    const int n0   = blockIdx.y * BN;
    const int z    = blockIdx.z;

    A    += (size_t)z * zA;
    WT   += (size_t)z * zB;
    bias += z * zbias;

    // loaders: stage = 64 k-elements per row (128B). A: 4 threads/row x 2 chunks.
    const int ar  = tid >> 2;            // 0..63
    const int awd = (tid & 3) << 3;      // word offset 0,8,16,24
    const uint32_t aval = ((m0 + ar) < Mrows) ? 16u : 0u;
    const bf16* agp = A + (size_t)(m0 + ar) * lda + (awd << 1);

    // B: BN=64 -> same as A; BN=32 -> 8 threads/row x 1 chunk
    const int br  = (BN == 64) ? (tid >> 2) : (tid >> 3);
    const int bwd = (BN == 64) ? ((tid & 3) << 3) : ((tid & 7) << 2);
    const bf16* bgp = WT + (size_t)(n0 + br) * ldb + (bwd << 1);

    // ldmatrix lane addressing (word units; ks in {0,8,16,24})
    const int a_lm_row = wm + (lane & 15);
    const int a_lm_col = (lane >> 4) << 2;
    const int b_lm_row = (BN == 64) ? (wn + ((lane >> 4) << 3) + (lane & 7))
                                    : (wn + (lane & 7));
    const int b_lm_col = ((lane >> 3) & 1) << 2;

    const int niter = Klen >> 6;   // K=64 per stage

    auto issue = [&](int kb, int s) {
        uint32_t sa = (uint32_t)__cvta_generic_to_shared(&ASA(s, ar, awd));
        CP_ASYNC16(sa,      agp + (kb << 6),     aval);
        CP_ASYNC16(sa + 16, agp + (kb << 6) + 8, aval);
        uint32_t sb = (uint32_t)__cvta_generic_to_shared(&BSA(s, br, bwd));
        CP_ASYNC16(sb, bgp + (kb << 6), 16u);
        if (BN == 64)
            CP_ASYNC16(sb + 16, bgp + (kb << 6) + 8, 16u);
    };

    float acc[2][NJ][4];
    #pragma unroll
    for (int i = 0; i < 2; i++)
        #pragma unroll
        for (int j = 0; j < NJ; j++)
            #pragma unroll
            for (int v = 0; v < 4; v++) acc[i][j][v] = 0.f;

    issue(0, 0); CP_COMMIT();
    issue(1, 1); CP_COMMIT();

    for (int it = 0; it < niter; it++) {
        const int s = it % 3;
        CP_WAIT1();               // oldest pending group (this stage) done
        __syncthreads();
        if (it + 2 < niter) issue(it + 2, (it + 2) % 3);
        CP_COMMIT();

        // 4 k16 steps; hoist fragments in pairs (R12 pattern)
        #pragma unroll
        for (int kp = 0; kp < 2; kp++) {
            uint32_t af[2][2][4];
            uint32_t bfr[2][NJ][2];
            #pragma unroll
            for (int kq = 0; kq < 2; kq++) {
                const int ks = ((kp << 1) + kq) << 3;
                #pragma unroll
                for (int mi = 0; mi < 2; mi++)
                    ldsm_x4(af[kq][mi][0], af[kq][mi][1], af[kq][mi][2], af[kq][mi][3],
                            &ASA(s, a_lm_row + (mi << 4), ks + a_lm_col));
                if (BN == 64) {
                    uint32_t r0, r1, r2, r3;
                    ldsm_x4(r0, r1, r2, r3, &BSA(s, b_lm_row, ks + b_lm_col));
                    bfr[kq][0][0] = r0; bfr[kq][0][1] = r1;
                    if (NJ > 1) { bfr[kq][NJ - 1][0] = r2; bfr[kq][NJ - 1][1] = r3; }
                } else {
                    ldsm_x2(bfr[kq][0][0], bfr[kq][0][1], &BSA(s, b_lm_row, ks + b_lm_col));
                }
            }
            #pragma unroll
            for (int kq = 0; kq < 2; kq++)
                #pragma unroll
                for (int mi = 0; mi < 2; mi++)
                    #pragma unroll
                    for (int nj = 0; nj < NJ; nj++)
                        MMA_BF16(acc[mi][nj], af[kq][mi], bfr[kq][nj]);
        }
    }

    #pragma unroll
    for (int nj = 0; nj < NJ; nj++) {
        const int cloc = n0 + wn + (nj << 3) + (tg << 1);
        const int col  = cloc + z * zC;
        const float2 bv = *(const float2*)&bias[cloc];
        #pragma unroll
        for (int mi = 0; mi < 2; mi++) {
            const int row0 = m0 + wm + (mi << 4) + g;
            const int row1 = row0 + 8;
            float2 v0 = make_float2(acc[mi][nj][0], acc[mi][nj][1]);
            float2 v1 = make_float2(acc[mi][nj][2], acc[mi][nj][3]);
            if (EPI == 0) {
                v0.x += bv.x; v0.y += bv.y; v1.x += bv.x; v1.y += bv.y;
            } else if (EPI == 1) {
                v0.x = fmaxf(v0.x + bv.x, 0.f); v0.y = fmaxf(v0.y + bv.y, 0.f);
                v1.x = fmaxf(v1.x + bv.x, 0.f); v1.y = fmaxf(v1.y + bv.y, 0.f);
            }
            if (row0 < Mrows) {
                if (EPI == 2) {
                    const float ws = wsum[(size_t)row0 * 8 + z];
                    v0.x += ws * bv.x; v0.y += ws * bv.y;
                }
                if (OBF) {
                    bf162 p = __floats2bfloat162_rn(v0.x, v0.y);
                    *(bf162*)((bf16*)Cg + (size_t)row0 * ldc + col) = p;
                } else {
                    *(float2*)((float*)Cg + (size_t)row0 * ldc + col) = v0;
                }
            }
            if (row1 < Mrows) {
                if (EPI == 2) {
                    const float ws = wsum[(size_t)row1 * 8 + z];
                    v1.x += ws * bv.x; v1.y += ws * bv.y;
                }
                if (OBF) {
                    bf162 p = __floats2bfloat162_rn(v1.x, v1.y);
                    *(bf162*)((bf16*)Cg + (size_t)row1 * ldc + col) = p;
                } else {
                    *(float2*)((float*)Cg + (size_t)row1 * ldc + col) = v1;
                }
            }
        }
    }
#undef ASA
#undef BSA
}

// ---------------- deformable sampling + aggregation (exact R12 form) ----------------
__global__ __launch_bounds__(256) void sample_agg_kernel(
    const float* __restrict__ value, const float* __restrict__ ref_points)
{
    const int r    = blockIdx.x;
    const int b    = r / NQ_;
    const int m    = threadIdx.x >> 5;
    const int lane = threadIdx.x & 31;

    const float rx = ref_points[r * 2 + 0];
    const float ry = ref_points[r * 2 + 1];

    float araw = (lane < 16) ? g_qout[(size_t)r * 384 + 256 + m * 16 + lane] : -1e30f;
    float amax = araw;
    #pragma unroll
    for (int o = 8; o; o >>= 1) amax = fmaxf(amax, __shfl_xor_sync(FULLMASK, amax, o, 16));
    float e = (lane < 16) ? __expf(araw - amax) : 0.f;
    float es = e;
    #pragma unroll
    for (int o = 8; o; o >>= 1) es += __shfl_xor_sync(FULLMASK, es, o, 16);
    const float anorm = e / es;

    const float offv = g_qout[(size_t)r * 384 + m * 32 + lane];

    float a0[4] = {0.f, 0.f, 0.f, 0.f};
    float a1[4] = {0.f, 0.f, 0.f, 0.f};
    float wl_acc = 0.f;

    const int Hs[4]  = {92, 46, 23, 12};
    const int Wls[4] = {160, 80, 40, 20};
    const int St[4]  = {0, 14720, 18400, 19320};
    const float* vb = value + (size_t)b * S_ * C_;

#define ACCUM(ptr, wgt) do {                                          \
        const float4* _p4 = (const float4*)(ptr);                     \
        float4 _v0 = _p4[lane];                                       \
        float4 _v1 = _p4[32 + lane];                                  \
        a0[0] = fmaf(wgt, _v0.x, a0[0]);                              \
        a0[1] = fmaf(wgt, _v0.y, a0[1]);                              \
        a0[2] = fmaf(wgt, _v0.z, a0[2]);                              \
        a0[3] = fmaf(wgt, _v0.w, a0[3]);                              \
        a1[0] = fmaf(wgt, _v1.x, a1[0]);                              \
        a1[1] = fmaf(wgt, _v1.y, a1[1]);                              \
        a1[2] = fmaf(wgt, _v1.z, a1[2]);                              \
        a1[3] = fmaf(wgt, _v1.w, a1[3]);                              \
    } while (0)

    #pragma unroll
    for (int l = 0; l < 4; l++) {
        const int Hl = Hs[l], Wl = Wls[l];
        const float invW = 1.f / (float)Wl, invH = 1.f / (float)Hl;
        const float* lb = vb + (size_t)St[l] * C_;

        const int c   = lane & 15;
        const int ptg = l * 4 + (c >> 2);
        const float a  = __shfl_sync(FULLMASK, anorm, ptg);
        const float ox = __shfl_sync(FULLMASK, offv, 2 * ptg);
        const float oy = __shfl_sync(FULLMASK, offv, 2 * ptg + 1);
        const float x = (rx + ox * invW) * (float)Wl - 0.5f;
        const float y = (ry + oy * invH) * (float)Hl - 0.5f;
        const float xf = floorf(x), yf = floorf(y);
        const float lx = x - xf, ly = y - yf;
        const int xi = (int)xf + (c & 1);
        const int yi = (int)yf + ((c >> 1) & 1);
        const float wx = (c & 1) ? lx : (1.f - lx);
        const float wy = ((c >> 1) & 1) ? ly : (1.f - ly);
        const float w = a * wx * wy;
        const bool valid = (lane < 16) &&
                           ((unsigned)xi < (unsigned)Wl) &&
                           ((unsigned)yi < (unsigned)Hl);
        const int key = valid ? (yi * Wl + xi) : -1;
        const float wl = valid ? w : 0.f;
        wl_acc += wl;

        const unsigned mm = __match_any_sync(FULLMASK, key);

        float wtot = 0.f;
        #pragma unroll
        for (int j = 0; j < 16; j++) {
            const float wj = __shfl_sync(FULLMASK, wl, j);
            if ((mm >> j) & 1u) wtot += wj;
        }
        const bool leader = valid && ((int)(__ffs(mm) - 1) == lane);

        unsigned bal = __ballot_sync(FULLMASK, leader);
        while (bal) {
            const int src = __ffs(bal) - 1;
            bal &= bal - 1;
            const int   idx = __shfl_sync(FULLMASK, key, src);
            const float wt  = __shfl_sync(FULLMASK, wtot, src);
            ACCUM(lb + (size_t)idx * C_, wt);
        }
    }
#undef ACCUM

    float wsum = wl_acc;
    #pragma unroll
    for (int o = 16; o; o >>= 1) wsum += __shfl_xor_sync(FULLMASK, wsum, o);

    bf16* ag = g_aggh + ((size_t)r * M_ + m) * C_;
    {
        bf162 p0 = __floats2bfloat162_rn(a0[0], a0[1]);
        bf162 p1 = __floats2bfloat162_rn(a0[2], a0[3]);
        uint2 u; u.x = *(uint32_t*)&p0; u.y = *(uint32_t*)&p1;
        *(uint2*)(ag + lane * 4) = u;
        p0 = __floats2bfloat162_rn(a1[0], a1[1]);
        p1 = __floats2bfloat162_rn(a1[2], a1[3]);
        u.x = *(uint32_t*)&p0; u.y = *(uint32_t*)&p1;
        *(uint2*)(ag + 128 + lane * 4) = u;
    }
    if (lane == 0) g_wsum[(size_t)r * M_ + m] = wsum;
}

// ---------------- LayerNorm helpers (R12 block form) ----------------
__global__ __launch_bounds__(256) void ln1_kernel(
    const float* __restrict__ query,
    const float* __restrict__ lw, const float* __restrict__ lb)
{
    const int r = blockIdx.x, t = threadIdx.x;
    const size_t idx = (size_t)r * C_ + t;
    float v = query[idx] + g_feat[idx];

    __shared__ float s1[8], s2[8];
    float sum = v, sq = v * v;
    #pragma unroll
    for (int o = 16; o; o >>= 1) {
        sum += __shfl_xor_sync(FULLMASK, sum, o);
        sq  += __shfl_xor_sync(FULLMASK, sq, o);
    }
    const int lane = t & 31, wp = t >> 5;
    if (lane == 0) { s1[wp] = sum; s2[wp] = sq; }
    __syncthreads();
    float tot = 0.f, totq = 0.f;
    #pragma unroll
    for (int i = 0; i < 8; i++) { tot += s1[i]; totq += s2[i]; }
    const float mu  = tot * (1.f / 256.f);
    const float var = totq * (1.f / 256.f) - mu * mu;
    const float rs  = rsqrtf(var + 1e-6f);
    const float o   = (v - mu) * rs * lw[t] + lb[t];
    g_x1[idx]  = o;
    g_x1h[idx] = __float2bfloat16_rn(o);
}

__global__ __launch_bounds__(256) void ln2_cls_kernel(
    const float* __restrict__ lw, const float* __restrict__ lb,
    const float* __restrict__ wcls, const float* __restrict__ bcls,
    float* __restrict__ out)
{
    const int r = blockIdx.x, t = threadIdx.x;
    const size_t idx = (size_t)r * C_ + t;
    float v = g_x1[idx] + g_h2[idx];

    __shared__ float s1[8], s2[8];
    __shared__ float sred[8][10];
    float sum = v, sq = v * v;
    #pragma unroll
    for (int o = 16; o; o >>= 1) {
        sum += __shfl_xor_sync(FULLMASK, sum, o);
        sq  += __shfl_xor_sync(FULLMASK, sq, o);
    }
    const int lane = t & 31, wp = t >> 5;
    if (lane == 0) { s1[wp] = sum; s2[wp] = sq; }
    __syncthreads();
    float tot = 0.f, totq = 0.f;
    #pragma unroll
    for (int i = 0; i < 8; i++) { tot += s1[i]; totq += s2[i]; }
    const float mu  = tot * (1.f / 256.f);
    const float var = totq * (1.f / 256.f) - mu * mu;
    const float rs  = rsqrtf(var + 1e-6f);
    const float x2  = (v - mu) * rs * lw[t] + lb[t];

    float pr[10];
    #pragma unroll
    for (int j = 0; j < 10; j++) pr[j] = x2 * wcls[t * 10 + j];
    #pragma unroll
    for (int o = 16; o; o >>= 1)
        #pragma unroll
        for (int j = 0; j < 10; j++) pr[j] += __shfl_xor_sync(FULLMASK, pr[j], o);
    if (lane == 0)
        #pragma unroll
        for (int j = 0; j < 10; j++) sred[wp][j] = pr[j];
    __syncthreads();
    if (t < 10) {
        float s = bcls[t];
        #pragma unroll
        for (int i = 0; i < 8; i++) s += sred[i][t];
        out[(size_t)r * NC_ + t] = s;
    }
}

// ---------------- launch ----------------
#define SMEM64 ((3*64*36 + 3*64*36) * 4)   // 55296
#define SMEM32 ((3*64*36 + 3*32*36) * 4)   // 41472
#define PREP_BLOCKS ((98304 + 65536 + 262144 + 262144 + 65536 + R_*C_/4 + 255) / 256)

extern "C" void kernel_launch(void* const* d_in, const int* in_sizes, int n_in,
                              void* d_out, int out_size)
{
    const float* query  = (const float*)d_in[0];
    const float* value  = (const float*)d_in[1];
    const float* refp   = (const float*)d_in[2];
    const float* w_value= (const float*)d_in[3];
    const float* b_value= (const float*)d_in[4];
    const float* w_off  = (const float*)d_in[5];
    const float* b_off  = (const float*)d_in[6];
    const float* w_attn = (const float*)d_in[7];
    const float* b_attn = (const float*)d_in[8];
    const float* w_out  = (const float*)d_in[9];
    const float* b_out  = (const float*)d_in[10];
    const float* ln1w   = (const float*)d_in[11];
    const float* ln1b   = (const float*)d_in[12];
    const float* w_ffn1 = (const float*)d_in[13];
    const float* b_ffn1 = (const float*)d_in[14];
    const float* w_ffn2 = (const float*)d_in[15];
    const float* b_ffn2 = (const float*)d_in[16];
    const float* ln2w   = (const float*)d_in[17];
    const float* ln2b   = (const float*)d_in[18];
    const float* w_cls  = (const float*)d_in[19];
    const float* b_cls  = (const float*)d_in[20];
    float* out = (float*)d_out;

    float *p_qout, *p_wsum, *p_feat, *p_x1, *p_h2, *p_bq;
    bf16  *p_aggh, *p_featvh, *p_x1h, *p_hh, *p_qbf;
    bf16  *p_wqTh, *p_woutTh, *p_f1Th, *p_f2Th, *p_wvTh;
    cudaGetSymbolAddress((void**)&p_qout,   g_qout);
    cudaGetSymbolAddress((void**)&p_aggh,   g_aggh);
    cudaGetSymbolAddress((void**)&p_wsum,   g_wsum);
    cudaGetSymbolAddress((void**)&p_featvh, g_featvh);
    cudaGetSymbolAddress((void**)&p_feat,   g_feat);
    cudaGetSymbolAddress((void**)&p_x1,     g_x1);
    cudaGetSymbolAddress((void**)&p_x1h,    g_x1h);
    cudaGetSymbolAddress((void**)&p_hh,     g_hh);
    cudaGetSymbolAddress((void**)&p_h2,     g_h2);
    cudaGetSymbolAddress((void**)&p_qbf,    g_qbf);
    cudaGetSymbolAddress((void**)&p_wqTh,   g_wqTh);
    cudaGetSymbolAddress((void**)&p_bq,     g_bq);
    cudaGetSymbolAddress((void**)&p_woutTh, g_woutTh);
    cudaGetSymbolAddress((void**)&p_f1Th,   g_f1Th);
    cudaGetSymbolAddress((void**)&p_f2Th,   g_f2Th);
    cudaGetSymbolAddress((void**)&p_wvTh,   g_wvTh);

    cudaFuncSetAttribute(gemm_bf<64,0,0>, cudaFuncAttributeMaxDynamicSharedMemorySize, SMEM64);
    cudaFuncSetAttribute(gemm_bf<64,1,1>, cudaFuncAttributeMaxDynamicSharedMemorySize, SMEM64);
    cudaFuncSetAttribute(gemm_bf<32,2,1>, cudaFuncAttributeMaxDynamicSharedMemorySize, SMEM32);

    // 0. weight + query bf16 prep (exact grid)
    prep_weights<<<PREP_BLOCKS, 256>>>(query, w_off, w_attn, b_off, b_attn,
                                       w_out, w_ffn1, w_ffn2, w_value);
    // 1. fused query projection: [off | attn] = q @ [w_off | w_attn]   grid 678
    gemm_bf<64,0,0><<<dim3(MT64, 6), 256, SMEM64>>>(p_qbf, C_, 0, p_wqTh, 256, 0, p_bq, 0,
                                                    nullptr, p_qout, 384, 0, R_, 256);
    // 2. deformable sampling + weighted aggregation (R12 form)
    sample_agg_kernel<<<R_, 256>>>(value, refp);
    // 3. per-head value projection (thin GEMM N=32 per head)   grid 904
    gemm_bf<32,2,1><<<dim3(MT64, 1, M_), 256, SMEM32>>>(p_aggh, 2048, 256, p_wvTh, 256, 8192,
                                                        b_value, 32, p_wsum,
                                                        p_featvh, C_, 32, R_, 256);
    // 4. output projection (fp32 out for LN)   grid 452
    gemm_bf<64,0,0><<<dim3(MT64, 4), 256, SMEM64>>>(p_featvh, C_, 0, p_woutTh, 256, 0, b_out, 0,
                                                    nullptr, p_feat, C_, 0, R_, 256);
    // 5. residual + LN1 (block per row, R12 form)
    ln1_kernel<<<R_, 256>>>(query, ln1w, ln1b);
    // 6. FFN   grids 1808 / 452
    gemm_bf<64,1,1><<<dim3(MT64, 16), 256, SMEM64>>>(p_x1h, C_, 0, p_f1Th, 256, 0, b_ffn1, 0,
                                                     nullptr, p_hh, FFN_, 0, R_, 256);
    gemm_bf<64,0,0><<<dim3(MT64, 4), 256, SMEM64>>>(p_hh, FFN_, 0, p_f2Th, 1024, 0, b_ffn2, 0,
                                                    nullptr, p_h2, C_, 0, R_, 1024);
    // 7. residual + LN2 + classifier (block per row, R12 form)
    ln2_cls_kernel<<<R_, 256>>>(ln2w, ln2b, w_cls, b_cls, out);
}

// round 17
// speedup vs baseline: 1.0953x; 1.0187x over previous
#include <cuda_runtime.h>
#include <cuda_bf16.h>
#include <math.h>
#include <stdint.h>

#define FULLMASK 0xffffffffu

// Problem constants
#define B_    8
#define NQ_   900
#define C_    256
#define M_    8
#define D_    32
#define S_    19560
#define FFN_  1024
#define NC_   10
#define R_    (B_*NQ_)            // 7200 rows
#define MT64  ((R_ + 63) / 64)    // 113 M tiles (BM=64)

typedef __nv_bfloat16  bf16;
typedef __nv_bfloat162 bf162;

// ---------------- scratch (static device globals) ----------------
__device__ float g_qout [R_ * 384];        // [off(256) | attn(128)] per row (fp32)
__device__ bf16  g_aggh [R_ * M_ * C_];    // aggregated value rows, bf16
__device__ float g_wsum [R_ * M_];
__device__ bf16  g_featvh[R_ * C_];        // per-head projected features, bf16
__device__ float g_feat [R_ * C_];         // after w_out (fp32, LN input)
__device__ float g_x1   [R_ * C_];         // after LN1 (fp32, residual)
__device__ bf16  g_x1h  [R_ * C_];         // after LN1 (bf16, ffn1 input)
__device__ bf16  g_hh   [R_ * FFN_];       // FFN hidden, bf16
__device__ float g_h2   [R_ * C_];         // after w_ffn2 (fp32)
// bf16 weights [N, K] + bf16 query
__device__ bf16  g_qbf  [R_ * C_];
__device__ bf16  g_wqTh [384 * 256];
__device__ float g_bq   [384];
__device__ bf16  g_woutTh[256 * 256];
__device__ bf16  g_f1Th [1024 * 256];
__device__ bf16  g_f2Th [256 * 1024];
__device__ bf16  g_wvTh [M_ * D_ * 256];   // per-head value-proj slice [8][32][256]

// bf16 m16n8k16 warp MMA
#define MMA_BF16(c, a, b) \
    asm volatile("mma.sync.aligned.m16n8k16.row.col.f32.bf16.bf16.f32 " \
        "{%0,%1,%2,%3}, {%4,%5,%6,%7}, {%8,%9}, {%0,%1,%2,%3};" \
        : "+f"((c)[0]), "+f"((c)[1]), "+f"((c)[2]), "+f"((c)[3]) \
        : "r"((a)[0]), "r"((a)[1]), "r"((a)[2]), "r"((a)[3]), \
          "r"((b)[0]), "r"((b)[1]))

__device__ __forceinline__ void ldsm_x4(uint32_t& r0, uint32_t& r1, uint32_t& r2,
                                        uint32_t& r3, const void* p) {
    uint32_t a = (uint32_t)__cvta_generic_to_shared(p);
    asm volatile("ldmatrix.sync.aligned.m8n8.x4.shared.b16 {%0,%1,%2,%3}, [%4];"
                 : "=r"(r0), "=r"(r1), "=r"(r2), "=r"(r3) : "r"(a));
}
__device__ __forceinline__ void ldsm_x2(uint32_t& r0, uint32_t& r1, const void* p) {
    uint32_t a = (uint32_t)__cvta_generic_to_shared(p);
    asm volatile("ldmatrix.sync.aligned.m8n8.x2.shared.b16 {%0,%1}, [%2];"
                 : "=r"(r0), "=r"(r1) : "r"(a));
}

#define CP_ASYNC16(saddr, gaddr, srcsz) \
    asm volatile("cp.async.cg.shared.global [%0], [%1], 16, %2;" \
        :: "r"(saddr), "l"(gaddr), "r"(srcsz))
#define CP_COMMIT()  asm volatile("cp.async.commit_group;" ::: "memory")
#define CP_WAIT2()   asm volatile("cp.async.wait_group 2;" ::: "memory")

// ---------------- weight / activation prep (all bf16 conversions) ----------------
__global__ __launch_bounds__(256) void prep_weights(
    const float* __restrict__ query,
    const float* __restrict__ w_off, const float* __restrict__ w_attn,
    const float* __restrict__ b_off, const float* __restrict__ b_attn,
    const float* __restrict__ w_out_, const float* __restrict__ w_ffn1,
    const float* __restrict__ w_ffn2, const float* __restrict__ w_value)
{
    int idx = blockIdx.x * 256 + threadIdx.x;
    if (idx < 98304) {                                   // wqTh [384,256]
        int n = idx >> 8, k = idx & 255;
        g_wqTh[idx] = __float2bfloat16_rn((n < 256) ? w_off[k * 256 + n]
                                                    : w_attn[k * 128 + (n - 256)]);
        if (idx < 384) g_bq[idx] = (idx < 256) ? b_off[idx] : b_attn[idx - 256];
        return;
    }
    idx -= 98304;
    if (idx < 65536) {                                   // woutTh [256,256]
        int n = idx >> 8, k = idx & 255;
        g_woutTh[idx] = __float2bfloat16_rn(w_out_[k * 256 + n]);
        return;
    }
    idx -= 65536;
    if (idx < 262144) {                                  // f1Th [1024,256]
        int n = idx >> 8, k = idx & 255;
        g_f1Th[idx] = __float2bfloat16_rn(w_ffn1[k * 1024 + n]);
        return;
    }
    idx -= 262144;
    if (idx < 262144) {                                  // f2Th [256,1024]
        int n = idx >> 10, k = idx & 1023;
        g_f2Th[idx] = __float2bfloat16_rn(w_ffn2[k * 256 + n]);
        return;
    }
    idx -= 262144;
    if (idx < 65536) {                                   // wvTh [8][32][256]
        int m = idx >> 13, n = (idx >> 8) & 31, k = idx & 255;
        g_wvTh[idx] = __float2bfloat16_rn(w_value[k * 256 + m * 32 + n]);
        return;
    }
    idx -= 65536;
    if (idx < R_ * C_ / 4) {                             // qbf (float4 -> 4 bf16)
        float4 v = *(const float4*)&query[idx * 4];
        bf162 p0 = __floats2bfloat162_rn(v.x, v.y);
        bf162 p1 = __floats2bfloat162_rn(v.z, v.w);
        uint2 u;
        u.x = *(uint32_t*)&p0; u.y = *(uint32_t*)&p1;
        *(uint2*)&g_qbf[idx * 4] = u;
        return;
    }
}

// ---------------- bf16 mma GEMM: BM=64, ldmatrix + 4-stage cp.async ----------------
// (exact R12 kernel — best measured configuration)
template<int BN, int EPI, int OBF>
__global__ __launch_bounds__(256) void gemm_bf(
    const bf16* __restrict__ A, int lda, int zA,
    const bf16* __restrict__ WT, int ldb, int zB,
    const float* __restrict__ bias, int zbias,
    const float* __restrict__ wsum,
    void* __restrict__ Cg, int ldc, int zC,
    int Mrows, int Klen)
{
    constexpr int WN = BN / 4;
    constexpr int NJ = WN / 8;
    extern __shared__ float smp[];
    float* As = smp;                    // [4][64][20]
    float* Bs = smp + 4 * 64 * 20;      // [4][BN][20]
#define ASA(s,r,c) As[(((s) << 6) + (r)) * 20 + (c)]
#define BSA(s,r,c) Bs[((s) * BN + (r)) * 20 + (c)]

    const int tid  = threadIdx.x;
    const int wid  = tid >> 5, lane = tid & 31;
    const int g    = lane >> 2, tg = lane & 3;
    const int wm   = (wid & 1) << 5;
    const int wn   = (wid >> 1) * WN;
    const int m0   = blockIdx.x * 64;
    const int n0   = blockIdx.y * BN;
    const int z    = blockIdx.z;

    A    += (size_t)z * zA;
    WT   += (size_t)z * zB;
    bias += z * zbias;

    const int ar  = tid >> 2;
    const int aw  = (tid & 3) << 2;
    const int br  = tid >> 2;
    const int bw  = (tid & 3) << 2;
    const uint32_t aval = ((m0 + ar) < Mrows) ? 16u : 0u;
    const bool bldr = (BN == 64) || (tid < 128);
    const bf16* agp = A  + (size_t)(m0 + ar) * lda + (aw << 1);
    const bf16* bgp = WT + (size_t)(n0 + br) * ldb + (bw << 1);

    const int a_lm_row = wm + (lane & 15);
    const int a_lm_col = (lane >> 4) << 2;
    const int b_lm_row = (BN == 64) ? (wn + ((lane >> 4) << 3) + (lane & 7))
                                    : (wn + (lane & 7));
    const int b_lm_col = ((lane >> 3) & 1) << 2;

    const int niter = Klen >> 5;

    auto issue = [&](int kb, int s) {
        uint32_t sa = (uint32_t)__cvta_generic_to_shared(&ASA(s, ar, aw));
        CP_ASYNC16(sa, agp + (kb << 5), aval);
        if (bldr) {
            uint32_t sb = (uint32_t)__cvta_generic_to_shared(&BSA(s, br, bw));
            CP_ASYNC16(sb, bgp + (kb << 5), 16u);
        }
    };

    float acc[2][NJ][4];
    #pragma unroll
    for (int i = 0; i < 2; i++)
        #pragma unroll
        for (int j = 0; j < NJ; j++)
            #pragma unroll
            for (int v = 0; v < 4; v++) acc[i][j][v] = 0.f;

    issue(0, 0); CP_COMMIT();
    issue(1, 1); CP_COMMIT();
    issue(2, 2); CP_COMMIT();

    for (int it = 0; it < niter; it++) {
        const int s = it & 3;
        CP_WAIT2();
        __syncthreads();
        if (it + 3 < niter) issue(it + 3, (it + 3) & 3);
        CP_COMMIT();

        uint32_t af[2][2][4];
        uint32_t bfr[2][NJ][2];
        #pragma unroll
        for (int kq = 0; kq < 2; kq++) {
            const int ks = kq << 3;
            #pragma unroll
            for (int mi = 0; mi < 2; mi++)
                ldsm_x4(af[kq][mi][0], af[kq][mi][1], af[kq][mi][2], af[kq][mi][3],
                        &ASA(s, a_lm_row + (mi << 4), ks + a_lm_col));
            if (BN == 64) {
                uint32_t r0, r1, r2, r3;
                ldsm_x4(r0, r1, r2, r3, &BSA(s, b_lm_row, ks + b_lm_col));
                bfr[kq][0][0] = r0; bfr[kq][0][1] = r1;
                if (NJ > 1) { bfr[kq][NJ - 1][0] = r2; bfr[kq][NJ - 1][1] = r3; }
            } else {
                ldsm_x2(bfr[kq][0][0], bfr[kq][0][1], &BSA(s, b_lm_row, ks + b_lm_col));
            }
        }
        #pragma unroll
        for (int kq = 0; kq < 2; kq++)
            #pragma unroll
            for (int mi = 0; mi < 2; mi++)
                #pragma unroll
                for (int nj = 0; nj < NJ; nj++)
                    MMA_BF16(acc[mi][nj], af[kq][mi], bfr[kq][nj]);
    }

    #pragma unroll
    for (int nj = 0; nj < NJ; nj++) {
        const int cloc = n0 + wn + (nj << 3) + (tg << 1);
        const int col  = cloc + z * zC;
        const float2 bv = *(const float2*)&bias[cloc];
        #pragma unroll
        for (int mi = 0; mi < 2; mi++) {
            const int row0 = m0 + wm + (mi << 4) + g;
            const int row1 = row0 + 8;
            float2 v0 = make_float2(acc[mi][nj][0], acc[mi][nj][1]);
            float2 v1 = make_float2(acc[mi][nj][2], acc[mi][nj][3]);
            if (EPI == 0) {
                v0.x += bv.x; v0.y += bv.y; v1.x += bv.x; v1.y += bv.y;
            } else if (EPI == 1) {
                v0.x = fmaxf(v0.x + bv.x, 0.f); v0.y = fmaxf(v0.y + bv.y, 0.f);
                v1.x = fmaxf(v1.x + bv.x, 0.f); v1.y = fmaxf(v1.y + bv.y, 0.f);
            }
            if (row0 < Mrows) {
                if (EPI == 2) {
                    const float ws = wsum[(size_t)row0 * 8 + z];
                    v0.x += ws * bv.x; v0.y += ws * bv.y;
                }
                if (OBF) {
                    bf162 p = __floats2bfloat162_rn(v0.x, v0.y);
                    *(bf162*)((bf16*)Cg + (size_t)row0 * ldc + col) = p;
                } else {
                    *(float2*)((float*)Cg + (size_t)row0 * ldc + col) = v0;
                }
            }
            if (row1 < Mrows) {
                if (EPI == 2) {
                    const float ws = wsum[(size_t)row1 * 8 + z];
                    v1.x += ws * bv.x; v1.y += ws * bv.y;
                }
                if (OBF) {
                    bf162 p = __floats2bfloat162_rn(v1.x, v1.y);
                    *(bf162*)((bf16*)Cg + (size_t)row1 * ldc + col) = p;
                } else {
                    *(float2*)((float*)Cg + (size_t)row1 * ldc + col) = v1;
                }
            }
        }
    }
#undef ASA
#undef BSA
}

// ---------------- deformable sampling + aggregation (exact R12 form) ----------------
__global__ __launch_bounds__(256) void sample_agg_kernel(
    const float* __restrict__ value, const float* __restrict__ ref_points)
{
    const int r    = blockIdx.x;
    const int b    = r / NQ_;
    const int m    = threadIdx.x >> 5;
    const int lane = threadIdx.x & 31;

    const float rx = ref_points[r * 2 + 0];
    const float ry = ref_points[r * 2 + 1];

    float araw = (lane < 16) ? g_qout[(size_t)r * 384 + 256 + m * 16 + lane] : -1e30f;
    float amax = araw;
    #pragma unroll
    for (int o = 8; o; o >>= 1) amax = fmaxf(amax, __shfl_xor_sync(FULLMASK, amax, o, 16));
    float e = (lane < 16) ? __expf(araw - amax) : 0.f;
    float es = e;
    #pragma unroll
    for (int o = 8; o; o >>= 1) es += __shfl_xor_sync(FULLMASK, es, o, 16);
    const float anorm = e / es;

    const float offv = g_qout[(size_t)r * 384 + m * 32 + lane];

    float a0[4] = {0.f, 0.f, 0.f, 0.f};
    float a1[4] = {0.f, 0.f, 0.f, 0.f};
    float wl_acc = 0.f;

    const int Hs[4]  = {92, 46, 23, 12};
    const int Wls[4] = {160, 80, 40, 20};
    const int St[4]  = {0, 14720, 18400, 19320};
    const float* vb = value + (size_t)b * S_ * C_;

#define ACCUM(ptr, wgt) do {                                          \
        const float4* _p4 = (const float4*)(ptr);                     \
        float4 _v0 = _p4[lane];                                       \
        float4 _v1 = _p4[32 + lane];                                  \
        a0[0] = fmaf(wgt, _v0.x, a0[0]);                              \
        a0[1] = fmaf(wgt, _v0.y, a0[1]);                              \
        a0[2] = fmaf(wgt, _v0.z, a0[2]);                              \
        a0[3] = fmaf(wgt, _v0.w, a0[3]);                              \
        a1[0] = fmaf(wgt, _v1.x, a1[0]);                              \
        a1[1] = fmaf(wgt, _v1.y, a1[1]);                              \
        a1[2] = fmaf(wgt, _v1.z, a1[2]);                              \
        a1[3] = fmaf(wgt, _v1.w, a1[3]);                              \
    } while (0)

    #pragma unroll
    for (int l = 0; l < 4; l++) {
        const int Hl = Hs[l], Wl = Wls[l];
        const float invW = 1.f / (float)Wl, invH = 1.f / (float)Hl;
        const float* lb = vb + (size_t)St[l] * C_;

        const int c   = lane & 15;
        const int ptg = l * 4 + (c >> 2);
        const float a  = __shfl_sync(FULLMASK, anorm, ptg);
        const float ox = __shfl_sync(FULLMASK, offv, 2 * ptg);
        const float oy = __shfl_sync(FULLMASK, offv, 2 * ptg + 1);
        const float x = (rx + ox * invW) * (float)Wl - 0.5f;
        const float y = (ry + oy * invH) * (float)Hl - 0.5f;
        const float xf = floorf(x), yf = floorf(y);
        const float lx = x - xf, ly = y - yf;
        const int xi = (int)xf + (c & 1);
        const int yi = (int)yf + ((c >> 1) & 1);
        const float wx = (c & 1) ? lx : (1.f - lx);
        const float wy = ((c >> 1) & 1) ? ly : (1.f - ly);
        const float w = a * wx * wy;
        const bool valid = (lane < 16) &&
                           ((unsigned)xi < (unsigned)Wl) &&
                           ((unsigned)yi < (unsigned)Hl);
        const int key = valid ? (yi * Wl + xi) : -1;
        const float wl = valid ? w : 0.f;
        wl_acc += wl;

        const unsigned mm = __match_any_sync(FULLMASK, key);

        float wtot = 0.f;
        #pragma unroll
        for (int j = 0; j < 16; j++) {
            const float wj = __shfl_sync(FULLMASK, wl, j);
            if ((mm >> j) & 1u) wtot += wj;
        }
        const bool leader = valid && ((int)(__ffs(mm) - 1) == lane);

        unsigned bal = __ballot_sync(FULLMASK, leader);
        while (bal) {
            const int src = __ffs(bal) - 1;
            bal &= bal - 1;
            const int   idx = __shfl_sync(FULLMASK, key, src);
            const float wt  = __shfl_sync(FULLMASK, wtot, src);
            ACCUM(lb + (size_t)idx * C_, wt);
        }
    }
#undef ACCUM

    float wsum = wl_acc;
    #pragma unroll
    for (int o = 16; o; o >>= 1) wsum += __shfl_xor_sync(FULLMASK, wsum, o);

    bf16* ag = g_aggh + ((size_t)r * M_ + m) * C_;
    {
        bf162 p0 = __floats2bfloat162_rn(a0[0], a0[1]);
        bf162 p1 = __floats2bfloat162_rn(a0[2], a0[3]);
        uint2 u; u.x = *(uint32_t*)&p0; u.y = *(uint32_t*)&p1;
        *(uint2*)(ag + lane * 4) = u;
        p0 = __floats2bfloat162_rn(a1[0], a1[1]);
        p1 = __floats2bfloat162_rn(a1[2], a1[3]);
        u.x = *(uint32_t*)&p0; u.y = *(uint32_t*)&p1;
        *(uint2*)(ag + 128 + lane * 4) = u;
    }
    if (lane == 0) g_wsum[(size_t)r * M_ + m] = wsum;
}

// ---------------- LayerNorm helpers (R12 block form) ----------------
__global__ __launch_bounds__(256) void ln1_kernel(
    const float* __restrict__ query,
    const float* __restrict__ lw, const float* __restrict__ lb)
{
    const int r = blockIdx.x, t = threadIdx.x;
    const size_t idx = (size_t)r * C_ + t;
    float v = query[idx] + g_feat[idx];

    __shared__ float s1[8], s2[8];
    float sum = v, sq = v * v;
    #pragma unroll
    for (int o = 16; o; o >>= 1) {
        sum += __shfl_xor_sync(FULLMASK, sum, o);
        sq  += __shfl_xor_sync(FULLMASK, sq, o);
    }
    const int lane = t & 31, wp = t >> 5;
    if (lane == 0) { s1[wp] = sum; s2[wp] = sq; }
    __syncthreads();
    float tot = 0.f, totq = 0.f;
    #pragma unroll
    for (int i = 0; i < 8; i++) { tot += s1[i]; totq += s2[i]; }
    const float mu  = tot * (1.f / 256.f);
    const float var = totq * (1.f / 256.f) - mu * mu;
    const float rs  = rsqrtf(var + 1e-6f);
    const float o   = (v - mu) * rs * lw[t] + lb[t];
    g_x1[idx]  = o;
    g_x1h[idx] = __float2bfloat16_rn(o);
}

__global__ __launch_bounds__(256) void ln2_cls_kernel(
    const float* __restrict__ lw, const float* __restrict__ lb,
    const float* __restrict__ wcls, const float* __restrict__ bcls,
    float* __restrict__ out)
{
    const int r = blockIdx.x, t = threadIdx.x;
    const size_t idx = (size_t)r * C_ + t;
    float v = g_x1[idx] + g_h2[idx];

    __shared__ float s1[8], s2[8];
    __shared__ float sred[8][10];
    float sum = v, sq = v * v;
    #pragma unroll
    for (int o = 16; o; o >>= 1) {
        sum += __shfl_xor_sync(FULLMASK, sum, o);
        sq  += __shfl_xor_sync(FULLMASK, sq, o);
    }
    const int lane = t & 31, wp = t >> 5;
    if (lane == 0) { s1[wp] = sum; s2[wp] = sq; }
    __syncthreads();
    float tot = 0.f, totq = 0.f;
    #pragma unroll
    for (int i = 0; i < 8; i++) { tot += s1[i]; totq += s2[i]; }
    const float mu  = tot * (1.f / 256.f);
    const float var = totq * (1.f / 256.f) - mu * mu;
    const float rs  = rsqrtf(var + 1e-6f);
    const float x2  = (v - mu) * rs * lw[t] + lb[t];

    float pr[10];
    #pragma unroll
    for (int j = 0; j < 10; j++) pr[j] = x2 * wcls[t * 10 + j];
    #pragma unroll
    for (int o = 16; o; o >>= 1)
        #pragma unroll
        for (int j = 0; j < 10; j++) pr[j] += __shfl_xor_sync(FULLMASK, pr[j], o);
    if (lane == 0)
        #pragma unroll
        for (int j = 0; j < 10; j++) sred[wp][j] = pr[j];
    __syncthreads();
    if (t < 10) {
        float s = bcls[t];
        #pragma unroll
        for (int i = 0; i < 8; i++) s += sred[i][t];
        out[(size_t)r * NC_ + t] = s;
    }
}

// ---------------- launch ----------------
#define SMEM64 ((4*64*20 + 4*64*20) * 4)   // 40960
#define SMEM32 ((4*64*20 + 4*32*20) * 4)   // 30720
#define PREP_BLOCKS ((98304 + 65536 + 262144 + 262144 + 65536 + R_*C_/4 + 255) / 256)

extern "C" void kernel_launch(void* const* d_in, const int* in_sizes, int n_in,
                              void* d_out, int out_size)
{
    const float* query  = (const float*)d_in[0];
    const float* value  = (const float*)d_in[1];
    const float* refp   = (const float*)d_in[2];
    const float* w_value= (const float*)d_in[3];
    const float* b_value= (const float*)d_in[4];
    const float* w_off  = (const float*)d_in[5];
    const float* b_off  = (const float*)d_in[6];
    const float* w_attn = (const float*)d_in[7];
    const float* b_attn = (const float*)d_in[8];
    const float* w_out  = (const float*)d_in[9];
    const float* b_out  = (const float*)d_in[10];
    const float* ln1w   = (const float*)d_in[11];
    const float* ln1b   = (const float*)d_in[12];
    const float* w_ffn1 = (const float*)d_in[13];
    const float* b_ffn1 = (const float*)d_in[14];
    const float* w_ffn2 = (const float*)d_in[15];
    const float* b_ffn2 = (const float*)d_in[16];
    const float* ln2w   = (const float*)d_in[17];
    const float* ln2b   = (const float*)d_in[18];
    const float* w_cls  = (const float*)d_in[19];
    const float* b_cls  = (const float*)d_in[20];
    float* out = (float*)d_out;

    float *p_qout, *p_wsum, *p_feat, *p_x1, *p_h2, *p_bq;
    bf16  *p_aggh, *p_featvh, *p_x1h, *p_hh, *p_qbf;
    bf16  *p_wqTh, *p_woutTh, *p_f1Th, *p_f2Th, *p_wvTh;
    cudaGetSymbolAddress((void**)&p_qout,   g_qout);
    cudaGetSymbolAddress((void**)&p_aggh,   g_aggh);
    cudaGetSymbolAddress((void**)&p_wsum,   g_wsum);
    cudaGetSymbolAddress((void**)&p_featvh, g_featvh);
    cudaGetSymbolAddress((void**)&p_feat,   g_feat);
    cudaGetSymbolAddress((void**)&p_x1,     g_x1);
    cudaGetSymbolAddress((void**)&p_x1h,    g_x1h);
    cudaGetSymbolAddress((void**)&p_hh,     g_hh);
    cudaGetSymbolAddress((void**)&p_h2,     g_h2);
    cudaGetSymbolAddress((void**)&p_qbf,    g_qbf);
    cudaGetSymbolAddress((void**)&p_wqTh,   g_wqTh);
    cudaGetSymbolAddress((void**)&p_bq,     g_bq);
    cudaGetSymbolAddress((void**)&p_woutTh, g_woutTh);
    cudaGetSymbolAddress((void**)&p_f1Th,   g_f1Th);
    cudaGetSymbolAddress((void**)&p_f2Th,   g_f2Th);
    cudaGetSymbolAddress((void**)&p_wvTh,   g_wvTh);

    cudaFuncSetAttribute(gemm_bf<64,0,0>, cudaFuncAttributeMaxDynamicSharedMemorySize, SMEM64);
    cudaFuncSetAttribute(gemm_bf<64,1,1>, cudaFuncAttributeMaxDynamicSharedMemorySize, SMEM64);
    cudaFuncSetAttribute(gemm_bf<32,2,1>, cudaFuncAttributeMaxDynamicSharedMemorySize, SMEM32);

    // 0. weight + query bf16 prep (exact grid)
    prep_weights<<<PREP_BLOCKS, 256>>>(query, w_off, w_attn, b_off, b_attn,
                                       w_out, w_ffn1, w_ffn2, w_value);
    // 1. fused query projection: [off | attn] = q @ [w_off | w_attn]   grid 678
    gemm_bf<64,0,0><<<dim3(MT64, 6), 256, SMEM64>>>(p_qbf, C_, 0, p_wqTh, 256, 0, p_bq, 0,
                                                    nullptr, p_qout, 384, 0, R_, 256);
    // 2. deformable sampling + weighted aggregation (match_any dedup)
    sample_agg_kernel<<<R_, 256>>>(value, refp);
    // 3. per-head value projection (thin GEMM N=32 per head)   grid 904
    gemm_bf<32,2,1><<<dim3(MT64, 1, M_), 256, SMEM32>>>(p_aggh, 2048, 256, p_wvTh, 256, 8192,
                                                        b_value, 32, p_wsum,
                                                        p_featvh, C_, 32, R_, 256);
    // 4. output projection (fp32 out for LN)   grid 452
    gemm_bf<64,0,0><<<dim3(MT64, 4), 256, SMEM64>>>(p_featvh, C_, 0, p_woutTh, 256, 0, b_out, 0,
                                                    nullptr, p_feat, C_, 0, R_, 256);
    // 5. residual + LN1 (block per row)
    ln1_kernel<<<R_, 256>>>(query, ln1w, ln1b);
    // 6. FFN   grids 1808 / 452
    gemm_bf<64,1,1><<<dim3(MT64, 16), 256, SMEM64>>>(p_x1h, C_, 0, p_f1Th, 256, 0, b_ffn1, 0,
                                                     nullptr, p_hh, FFN_, 0, R_, 256);
    gemm_bf<64,0,0><<<dim3(MT64, 4), 256, SMEM64>>>(p_hh, FFN_, 0, p_f2Th, 1024, 0, b_ffn2, 0,
                                                    nullptr, p_h2, C_, 0, R_, 1024);
    // 7. residual + LN2 + classifier (block per row)
    ln2_cls_kernel<<<R_, 256>>>(ln2w, ln2b, w_cls, b_cls, out);
}